// round 4
// baseline (speedup 1.0000x reference)
#include <cuda_runtime.h>
#include <cuda.h>
#include <math.h>
#include <stdint.h>

// Problem constants
#define Tn   4096
#define Hn   2048
#define En   32
#define Kn   4
#define Fn   1408
#define F2n  2816
#define FSn  5632
#define FS2n 11264
#define RPAD (Tn*Kn + En*128)     // 20480 expanded rows, expert segs 128-aligned
#define MT_E (RPAD/128)           // 160 expert M-tiles

typedef signed char s8;

// ---------------- device scratch ----------------
__device__ __align__(1024) s8 g_gupT_h[(size_t)En*F2n*Hn];
__device__ __align__(1024) s8 g_gupT_m[(size_t)En*F2n*Hn];
__device__ __align__(1024) s8 g_dwnT_h[(size_t)En*Hn*Fn];
__device__ __align__(1024) s8 g_dwnT_m[(size_t)En*Hn*Fn];
__device__ __align__(1024) s8 g_sguT_h[(size_t)FS2n*Hn];
__device__ __align__(1024) s8 g_sguT_m[(size_t)FS2n*Hn];
__device__ __align__(1024) s8 g_sdnT_h[(size_t)Hn*FSn];
__device__ __align__(1024) s8 g_sdnT_m[(size_t)Hn*FSn];
__device__ __align__(1024) s8 g_hidq_h[(size_t)Tn*Hn];
__device__ __align__(1024) s8 g_hidq_m[(size_t)Tn*Hn];
__device__ __align__(1024) s8 g_dispq_h[(size_t)RPAD*Hn];
__device__ __align__(1024) s8 g_dispq_m[(size_t)RPAD*Hn];
__device__ __align__(1024) s8 g_actq_h[(size_t)RPAD*Fn];
__device__ __align__(1024) s8 g_actq_m[(size_t)RPAD*Fn];
__device__ __align__(1024) s8 g_sactq_h[(size_t)Tn*FSn];
__device__ __align__(1024) s8 g_sactq_m[(size_t)Tn*FSn];
__device__ float g_act [(size_t)RPAD * Fn];    // fp32 swiglu output (expert)
__device__ float g_sact[(size_t)Tn * FSn];     // fp32 swiglu output (shared)
__device__ float g_eout[(size_t)RPAD * Hn];
__device__ float g_sout[(size_t)Tn * Hn];
__device__ float g_scl_hid[Tn];
__device__ float g_scl_disp[RPAD];
__device__ float g_scl_act[RPAD];
__device__ float g_scl_sact[Tn];
__device__ unsigned g_wmax[66];                // |max| bits per weight matrix
__device__ int   g_row_token[RPAD];
__device__ int   g_row_id[Tn*Kn];
__device__ float g_rw[Tn*Kn];
__device__ float g_gate[Tn];
__device__ int   g_cnt[En];
__device__ int   g_off[En+1];
__device__ int   g_pos[Tn*Kn];
__device__ int   g_eidx[Tn*Kn];
__device__ int   g_tile_expert[MT_E];

// ---------------- PTX helpers ----------------
__device__ __forceinline__ uint32_t s2u(const void* p) {
    uint32_t a;
    asm("{ .reg .u64 t; cvta.to.shared.u64 t, %1; cvt.u32.u64 %0, t; }" : "=r"(a) : "l"(p));
    return a;
}
#define MBARRIER_INIT(addr, cnt) \
    asm volatile("mbarrier.init.shared.b64 [%0], %1;" :: "r"((uint32_t)(addr)), "r"((uint32_t)(cnt)) : "memory")
#define MBARRIER_EXPECT_TX(addr, bytes) \
    asm volatile("mbarrier.arrive.expect_tx.shared.b64 _, [%0], %1;" :: "r"((uint32_t)(addr)), "r"((uint32_t)(bytes)) : "memory")
#define MBARRIER_ARRIVE(addr) \
    asm volatile("mbarrier.arrive.shared.b64 _, [%0];" :: "r"((uint32_t)(addr)) : "memory")
#define MBARRIER_WAIT_PARITY(mbar_smem_addr, phase_parity) do { \
    uint32_t _mbar = (uint32_t)(mbar_smem_addr); \
    uint32_t _parity = (uint32_t)(phase_parity); \
    uint32_t _done; \
    asm volatile("{\n\t.reg .pred p;\n\t" \
        "mbarrier.try_wait.parity.acquire.cta.shared::cta.b64 p, [%1], %2;\n\t" \
        "selp.b32 %0, 1, 0, p;\n\t}" \
        : "=r"(_done) : "r"(_mbar), "r"(_parity) : "memory"); \
    if (!_done) { \
        asm volatile("{\n\t.reg .pred P1;\n\t" \
            "WAIT_LOOP_%=:\n\t" \
            "mbarrier.try_wait.parity.acquire.cta.shared::cta.b64 P1, [%0], %1, 0x989680;\n\t" \
            "@P1 bra.uni WAIT_DONE_%=;\n\t" \
            "bra.uni WAIT_LOOP_%=;\n\t" \
            "WAIT_DONE_%=:\n\t}" \
            :: "r"(_mbar), "r"(_parity) : "memory"); \
    } \
} while(0)
#define FENCE_PROXY_ASYNC() asm volatile("fence.proxy.async.shared::cta;" ::: "memory")

__device__ __forceinline__ void tma3(uint32_t dst, const CUtensorMap* m,
                                     int cx, int cy, int cz, uint32_t mbar) {
    asm volatile(
        "cp.async.bulk.tensor.3d.shared::cta.global.tile.mbarrier::complete_tx::bytes "
        "[%0], [%1, {%2, %3, %4}], [%5];"
        :: "r"(dst), "l"(m), "r"(cx), "r"(cy), "r"(cz), "r"(mbar) : "memory");
}
__device__ __forceinline__ void ldsm4(uint32_t* q, uint32_t addr) {
    asm volatile("ldmatrix.sync.aligned.m8n8.x4.shared.b16 {%0,%1,%2,%3}, [%4];"
        : "=r"(q[0]), "=r"(q[1]), "=r"(q[2]), "=r"(q[3]) : "r"(addr));
}
__device__ __forceinline__ void mma_s8(int* c, const uint32_t* a, uint32_t b0, uint32_t b1) {
    asm volatile("mma.sync.aligned.m16n8k32.row.col.s32.s8.s8.s32 "
        "{%0,%1,%2,%3}, {%4,%5,%6,%7}, {%8,%9}, {%0,%1,%2,%3};"
        : "+r"(c[0]), "+r"(c[1]), "+r"(c[2]), "+r"(c[3])
        : "r"(a[0]), "r"(a[1]), "r"(a[2]), "r"(a[3]), "r"(b0), "r"(b1));
}

// ---------------- routing ----------------
__global__ void k_init() {
    int i = blockIdx.x * blockDim.x + threadIdx.x;
    if (i < En)   g_cnt[i] = 0;
    if (i < 66)   g_wmax[i] = 0u;
    if (i < RPAD) g_row_token[i] = -1;
}

__global__ void k_router(const float* __restrict__ hs, const float* __restrict__ rw,
                         const float* __restrict__ gw) {
    __shared__ float sh[Hn];
    __shared__ float slog[En];
    __shared__ float sred[128];
    int t = blockIdx.x;
    const float* hrow = hs + (size_t)t * Hn;
    for (int i = threadIdx.x; i < Hn; i += 128) sh[i] = hrow[i];
    __syncthreads();
    int warp = threadIdx.x >> 5, lane = threadIdx.x & 31;
    #pragma unroll
    for (int eo = 0; eo < 8; eo++) {
        int e = (warp << 3) + eo;
        const float* w = rw + (size_t)e * Hn;
        float acc = 0.f;
        for (int h = lane; h < Hn; h += 32) acc = fmaf(sh[h], w[h], acc);
        #pragma unroll
        for (int o = 16; o; o >>= 1) acc += __shfl_down_sync(0xffffffffu, acc, o);
        if (lane == 0) slog[e] = acc;
    }
    float g = 0.f;
    for (int h = threadIdx.x; h < Hn; h += 128) g = fmaf(sh[h], gw[h], g);
    sred[threadIdx.x] = g;
    __syncthreads();
    for (int s = 64; s; s >>= 1) {
        if (threadIdx.x < s) sred[threadIdx.x] += sred[threadIdx.x + s];
        __syncthreads();
    }
    if (threadIdx.x == 0) {
        g_gate[t] = 1.f / (1.f + expf(-sred[0]));
        float mx = slog[0];
        for (int e = 1; e < En; e++) mx = fmaxf(mx, slog[e]);
        float p[En]; float sum = 0.f;
        for (int e = 0; e < En; e++) { p[e] = expf(slog[e] - mx); sum += p[e]; }
        float inv = 1.f / sum;
        for (int k = 0; k < Kn; k++) {
            int best = 0; float bp = p[0];
            for (int e = 1; e < En; e++) if (p[e] > bp) { bp = p[e]; best = e; }
            int i4 = t * Kn + k;
            g_eidx[i4] = best;
            g_rw[i4]   = bp * inv;
            g_pos[i4]  = atomicAdd(&g_cnt[best], 1);
            p[best] = -1.f;
        }
    }
}

__global__ void k_scan() {
    int o = 0; g_off[0] = 0;
    for (int e = 0; e < En; e++) { o += ((g_cnt[e] + 127) & ~127); g_off[e+1] = o; }
    for (int t = 0; t < MT_E; t++) {
        int r = t * 128, e = -1;
        for (int x = 0; x < En; x++)
            if (r >= g_off[x] && r < g_off[x] + g_cnt[x]) { e = x; break; }
        g_tile_expert[t] = e;
    }
}

__global__ void k_scatter() {
    int i = blockIdx.x * blockDim.x + threadIdx.x;
    if (i >= Tn * Kn) return;
    int e = g_eidx[i];
    int row = g_off[e] + g_pos[i];
    g_row_token[row] = i >> 2;
    g_row_id[i] = row;
}

// ---------------- weight max (per matrix) ----------------
__global__ void k_wmax(const float* __restrict__ W, size_t perMat, int base) {
    const float4* p = (const float4*)(W + (size_t)blockIdx.z * perMat);
    size_t n4 = perMat >> 2;
    float mx = 0.f;
    for (size_t i = (size_t)blockIdx.x * blockDim.x + threadIdx.x; i < n4;
         i += (size_t)gridDim.x * blockDim.x) {
        float4 v = p[i];
        mx = fmaxf(mx, fmaxf(fmaxf(fabsf(v.x), fabsf(v.y)), fmaxf(fabsf(v.z), fabsf(v.w))));
    }
    __shared__ float red[256];
    red[threadIdx.x] = mx; __syncthreads();
    for (int s = 128; s; s >>= 1) {
        if (threadIdx.x < s) red[threadIdx.x] = fmaxf(red[threadIdx.x], red[threadIdx.x + s]);
        __syncthreads();
    }
    if (threadIdx.x == 0) atomicMax(&g_wmax[base + blockIdx.z], __float_as_uint(red[0]));
}

// ---------------- transpose + 2-level int8 quantization ----------------
// W[e][Kd][Nd] fp32 -> WT[e][ndst][Kd] int8 hi/mid.  ILV interleaves gate/up cols.
template<int ILV>
__global__ void k_tquant(const float* __restrict__ W, s8* __restrict__ qh, s8* __restrict__ qm,
                         int Kd, int Nd, int HALF, int base) {
    __shared__ float s[32][33];
    int e = blockIdx.z;
    float mx = __uint_as_float(g_wmax[base + e]);
    float scl = mx > 0.f ? mx / 127.f : 1.f;
    float inv = 127.f / (mx > 0.f ? mx : 1.f);
    const float* Wp = W + (size_t)e * Kd * Nd;
    int n0 = blockIdx.x * 32, k0 = blockIdx.y * 32;
    int tx = threadIdx.x, ty = threadIdx.y;
    #pragma unroll
    for (int j = 0; j < 4; j++)
        s[ty + 8*j][tx] = Wp[(size_t)(k0 + ty + 8*j) * Nd + n0 + tx];
    __syncthreads();
    size_t ob = (size_t)e * Nd * Kd;
    #pragma unroll
    for (int j = 0; j < 4; j++) {
        float v = s[tx][ty + 8*j];
        int jsrc = n0 + ty + 8*j;
        int nd = ILV ? (jsrc < HALF ? 2*jsrc : 2*(jsrc - HALF) + 1) : jsrc;
        float q1 = rintf(v * inv);
        q1 = fminf(fmaxf(q1, -127.f), 127.f);
        float r = v - q1 * scl;
        float q2 = rintf(r * 254.f * inv);
        q2 = fminf(fmaxf(q2, -127.f), 127.f);
        size_t idx = ob + (size_t)nd * Kd + k0 + tx;
        qh[idx] = (s8)(int)q1;
        qm[idx] = (s8)(int)q2;
    }
}

// ---------------- per-row activation quantization ----------------
__global__ void k_quant_rows(const float* __restrict__ X, s8* __restrict__ qh,
                             s8* __restrict__ qm, float* __restrict__ sclv, int ncols) {
    extern __shared__ float buf[];
    __shared__ float red[256];
    int row = blockIdx.x;
    const float* xp = X + (size_t)row * ncols;
    float mx = 0.f;
    for (int i = threadIdx.x; i < ncols; i += 256) {
        float v = xp[i]; buf[i] = v; mx = fmaxf(mx, fabsf(v));
    }
    red[threadIdx.x] = mx; __syncthreads();
    for (int s = 128; s; s >>= 1) {
        if (threadIdx.x < s) red[threadIdx.x] = fmaxf(red[threadIdx.x], red[threadIdx.x + s]);
        __syncthreads();
    }
    mx = red[0];
    float scl = mx > 0.f ? mx / 127.f : 1.f;
    float inv = 127.f / (mx > 0.f ? mx : 1.f);
    if (threadIdx.x == 0) sclv[row] = scl;
    for (int i = threadIdx.x; i < ncols; i += 256) {
        float v = buf[i];
        float q1 = rintf(v * inv);
        q1 = fminf(fmaxf(q1, -127.f), 127.f);
        float r = v - q1 * scl;
        float q2 = rintf(r * 254.f * inv);
        q2 = fminf(fmaxf(q2, -127.f), 127.f);
        qh[(size_t)row * ncols + i] = (s8)(int)q1;
        qm[(size_t)row * ncols + i] = (s8)(int)q2;
    }
}

// ---------------- gather quantized hidden -> dispatched ----------------
__global__ void k_gather_q() {
    int row = blockIdx.x;
    int tid = threadIdx.x;   // 128 threads x 16B = 2048B
    int tok = g_row_token[row];
    int4* dh = (int4*)(g_dispq_h + (size_t)row * Hn);
    int4* dm = (int4*)(g_dispq_m + (size_t)row * Hn);
    if (tok >= 0) {
        dh[tid] = ((const int4*)(g_hidq_h + (size_t)tok * Hn))[tid];
        dm[tid] = ((const int4*)(g_hidq_m + (size_t)tok * Hn))[tid];
        if (tid == 0) g_scl_disp[row] = g_scl_hid[tok];
    } else {
        int4 z = make_int4(0,0,0,0);
        dh[tid] = z; dm[tid] = z;
        if (tid == 0) g_scl_disp[row] = 1.f;
    }
}

// ---------------- combine ----------------
__global__ void k_combine(float* __restrict__ out) {
    int t = blockIdx.y;
    int h = blockIdx.x * 256 + threadIdx.x;
    float acc = g_gate[t] * g_sout[(size_t)t * Hn + h];
    #pragma unroll
    for (int k = 0; k < Kn; k++) {
        int i4 = t * Kn + k;
        acc = fmaf(g_rw[i4], g_eout[(size_t)g_row_id[i4] * Hn + h], acc);
    }
    out[(size_t)t * Hn + h] = acc;
}

// ---------------- int8 2-level split GEMM via mma.sync.m16n8k32.s8 ----------------
// CTA tile 128x128, K-chunk 128 bytes (SW128 from TMA), 3-stage pipeline.
// 8 warps (2m x 4n), warp tile 64x32, two s32 accumulator groups (hh, cross).
// FUSE=1: epilogue does SwiGLU on interleaved (g,u) column pairs, writes act fp32.
#define STAGE_BYTES 65536
#define SMEM_CTRL   1024
#define GEMM_SMEM   (SMEM_CTRL + 3*STAGE_BYTES)

template<int GROUPED, int FUSE>
__global__ void __launch_bounds__(256, 1) k_mma8(
    const __grid_constant__ CUtensorMap mAh,
    const __grid_constant__ CUtensorMap mAm,
    const __grid_constant__ CUtensorMap mBh,
    const __grid_constant__ CUtensorMap mBm,
    float* __restrict__ C, const float* __restrict__ sclA,
    int matbase, int Kdim, int NcolsC)
{
    extern __shared__ __align__(1024) char smem[];
    const int mtile = blockIdx.y;
    int eid = 0;
    if (GROUPED) { eid = g_tile_expert[mtile]; if (eid < 0) return; }
    const int m0 = mtile * 128;
    const int n0 = blockIdx.x * 128;
    const int tid  = threadIdx.x;
    const int wid  = tid >> 5;
    const int lane = tid & 31;
    const int mw = (wid >> 2) * 64;
    const int nw = (wid & 3) * 32;
    const uint32_t sb = s2u(smem);
    if (tid == 0) {
        #pragma unroll
        for (int s = 0; s < 3; s++) {
            MBARRIER_INIT(sb + 8*s, 1);
            MBARRIER_INIT(sb + 24 + 8*s, 256);
        }
        FENCE_PROXY_ASYNC();
    }
    __syncthreads();

    const int nch = Kdim >> 7;
    const uint32_t st0 = sb + SMEM_CTRL;

    if (tid == 0) {
        #pragma unroll
        for (int c = 0; c < 3; c++) {
            uint32_t st = st0 + c * STAGE_BYTES;
            int kc = c << 7;
            MBARRIER_EXPECT_TX(sb + 8*c, STAGE_BYTES);
            tma3(st +     0, &mAh, kc, m0, 0,   sb + 8*c);
            tma3(st + 16384, &mAm, kc, m0, 0,   sb + 8*c);
            tma3(st + 32768, &mBh, kc, n0, eid, sb + 8*c);
            tma3(st + 49152, &mBm, kc, n0, eid, sb + 8*c);
        }
    }

    int accH[4][4][4], accC[4][4][4];
    #pragma unroll
    for (int i = 0; i < 4; i++)
        #pragma unroll
        for (int j = 0; j < 4; j++)
            #pragma unroll
            for (int q = 0; q < 4; q++) { accH[i][j][q] = 0; accC[i][j][q] = 0; }

    const int r15 = lane & 15;
    const int cs  = lane >> 4;

    int s = 0, ph = 0;
    for (int c = 0; c < nch; c++) {
        MBARRIER_WAIT_PARITY(sb + 8*s, ph);
        const uint32_t st = st0 + s * STAGE_BYTES;
        #pragma unroll
        for (int kk = 0; kk < 4; kk++) {
            uint32_t aH[16], aM[16], bH[8], bM[8];
            #pragma unroll
            for (int mi = 0; mi < 4; mi++) {
                int row = mw + mi * 16 + r15;
                uint32_t off = row * 128 + ((((kk << 1) | cs) ^ (row & 7)) << 4);
                ldsm4(aH + 4*mi, st + off);
                ldsm4(aM + 4*mi, st + 16384 + off);
            }
            #pragma unroll
            for (int nj = 0; nj < 2; nj++) {
                int row = nw + nj * 16 + r15;
                uint32_t off = row * 128 + ((((kk << 1) | cs) ^ (row & 7)) << 4);
                ldsm4(bH + 4*nj, st + 32768 + off);
                ldsm4(bM + 4*nj, st + 49152 + off);
            }
            #pragma unroll
            for (int mi = 0; mi < 4; mi++) {
                #pragma unroll
                for (int ni = 0; ni < 4; ni++) {
                    int nj = ni >> 1, hf = ni & 1;
                    uint32_t bh0 = bH[4*nj + hf], bh1 = bH[4*nj + 2 + hf];
                    uint32_t bm0 = bM[4*nj + hf], bm1 = bM[4*nj + 2 + hf];
                    mma_s8(accH[mi][ni], aH + 4*mi, bh0, bh1);
                    mma_s8(accC[mi][ni], aH + 4*mi, bm0, bm1);
                    mma_s8(accC[mi][ni], aM + 4*mi, bh0, bh1);
                }
            }
        }
        MBARRIER_ARRIVE(sb + 24 + 8*s);
        if (tid == 0 && c + 3 < nch) {
            MBARRIER_WAIT_PARITY(sb + 24 + 8*s, ph);
            int kc = (c + 3) << 7;
            MBARRIER_EXPECT_TX(sb + 8*s, STAGE_BYTES);
            tma3(st +     0, &mAh, kc, m0, 0,   sb + 8*s);
            tma3(st + 16384, &mAm, kc, m0, 0,   sb + 8*s);
            tma3(st + 32768, &mBh, kc, n0, eid, sb + 8*s);
            tma3(st + 49152, &mBm, kc, n0, eid, sb + 8*s);
        }
        if (++s == 3) { s = 0; ph ^= 1; }
    }

    // epilogue
    float mxb = __uint_as_float(g_wmax[matbase + (GROUPED ? eid : 0)]);
    float sB = mxb > 0.f ? mxb / 127.f : 1.f;
    const float i254 = 1.f / 254.f;
    const int er = lane >> 2;
    const int ec = (lane & 3) << 1;
    #pragma unroll
    for (int mi = 0; mi < 4; mi++) {
        int r0 = m0 + mw + mi * 16 + er;
        float sa0 = sclA[r0] * sB;
        float sa1 = sclA[r0 + 8] * sB;
        #pragma unroll
        for (int ni = 0; ni < 4; ni++) {
            float v0 = sa0 * (__int2float_rn(accH[mi][ni][0]) + __int2float_rn(accC[mi][ni][0]) * i254);
            float v1 = sa0 * (__int2float_rn(accH[mi][ni][1]) + __int2float_rn(accC[mi][ni][1]) * i254);
            float v2 = sa1 * (__int2float_rn(accH[mi][ni][2]) + __int2float_rn(accC[mi][ni][2]) * i254);
            float v3 = sa1 * (__int2float_rn(accH[mi][ni][3]) + __int2float_rn(accC[mi][ni][3]) * i254);
            if (FUSE) {
                // interleaved columns: even = gate, odd = up
                int j = (n0 + nw + ni * 8 + ec) >> 1;
                C[(size_t)r0 * NcolsC + j]       = v0 / (1.f + expf(-v0)) * v1;
                C[(size_t)(r0 + 8) * NcolsC + j] = v2 / (1.f + expf(-v2)) * v3;
            } else {
                int col = n0 + nw + ni * 8 + ec;
                *(float2*)(C + (size_t)r0 * NcolsC + col)       = make_float2(v0, v1);
                *(float2*)(C + (size_t)(r0 + 8) * NcolsC + col) = make_float2(v2, v3);
            }
        }
    }
}

// ---------------- host launch ----------------
typedef CUresult (*encode_fn_t)(CUtensorMap*, CUtensorMapDataType, cuuint32_t, void*,
                                const cuuint64_t*, const cuuint64_t*, const cuuint32_t*,
                                const cuuint32_t*, CUtensorMapInterleave, CUtensorMapSwizzle,
                                CUtensorMapL2promotion, CUtensorMapFloatOOBfill);

static void mkmap8(encode_fn_t enc, CUtensorMap* m, void* ptr,
                   uint64_t d0, uint64_t d1, uint64_t d2) {
    cuuint64_t dims[3] = {d0, d1, d2};
    cuuint64_t str[2]  = {d0, d0 * d1};
    cuuint32_t box[3]  = {128, 128, 1};
    cuuint32_t es[3]   = {1, 1, 1};
    enc(m, CU_TENSOR_MAP_DATA_TYPE_UINT8, 3, ptr, dims, str, box, es,
        CU_TENSOR_MAP_INTERLEAVE_NONE, CU_TENSOR_MAP_SWIZZLE_128B,
        CU_TENSOR_MAP_L2_PROMOTION_L2_128B, CU_TENSOR_MAP_FLOAT_OOB_FILL_NONE);
}

extern "C" void kernel_launch(void* const* d_in, const int* in_sizes, int n_in,
                              void* d_out, int out_size)
{
    const float* hs  = (const float*)d_in[0];
    const float* rw  = (const float*)d_in[1];
    const float* gup = (const float*)d_in[2];
    const float* dwn = (const float*)d_in[3];
    const float* sgu = (const float*)d_in[4];
    const float* sdn = (const float*)d_in[5];
    const float* sgw = (const float*)d_in[6];
    float* out = (float*)d_out;

    void* fp = nullptr;
    cudaDriverEntryPointQueryResult qr;
    cudaGetDriverEntryPointByVersion("cuTensorMapEncodeTiled", &fp, 12000,
                                     cudaEnableDefault, &qr);
    encode_fn_t enc = (encode_fn_t)fp;

    void *q_gupT_h, *q_gupT_m, *q_dwnT_h, *q_dwnT_m, *q_sguT_h, *q_sguT_m,
         *q_sdnT_h, *q_sdnT_m, *q_hid_h, *q_hid_m, *q_disp_h, *q_disp_m,
         *q_act_h, *q_act_m, *q_sact_h, *q_sact_m;
    float *p_act, *p_sact, *p_eout, *p_sout,
          *p_scl_hid, *p_scl_disp, *p_scl_act, *p_scl_sact;
    cudaGetSymbolAddress(&q_gupT_h, g_gupT_h); cudaGetSymbolAddress(&q_gupT_m, g_gupT_m);
    cudaGetSymbolAddress(&q_dwnT_h, g_dwnT_h); cudaGetSymbolAddress(&q_dwnT_m, g_dwnT_m);
    cudaGetSymbolAddress(&q_sguT_h, g_sguT_h); cudaGetSymbolAddress(&q_sguT_m, g_sguT_m);
    cudaGetSymbolAddress(&q_sdnT_h, g_sdnT_h); cudaGetSymbolAddress(&q_sdnT_m, g_sdnT_m);
    cudaGetSymbolAddress(&q_hid_h,  g_hidq_h); cudaGetSymbolAddress(&q_hid_m,  g_hidq_m);
    cudaGetSymbolAddress(&q_disp_h, g_dispq_h);cudaGetSymbolAddress(&q_disp_m, g_dispq_m);
    cudaGetSymbolAddress(&q_act_h,  g_actq_h); cudaGetSymbolAddress(&q_act_m,  g_actq_m);
    cudaGetSymbolAddress(&q_sact_h, g_sactq_h);cudaGetSymbolAddress(&q_sact_m, g_sactq_m);
    cudaGetSymbolAddress((void**)&p_act,  g_act);
    cudaGetSymbolAddress((void**)&p_sact, g_sact);
    cudaGetSymbolAddress((void**)&p_eout, g_eout);
    cudaGetSymbolAddress((void**)&p_sout, g_sout);
    cudaGetSymbolAddress((void**)&p_scl_hid,  g_scl_hid);
    cudaGetSymbolAddress((void**)&p_scl_disp, g_scl_disp);
    cudaGetSymbolAddress((void**)&p_scl_act,  g_scl_act);
    cudaGetSymbolAddress((void**)&p_scl_sact, g_scl_sact);

    CUtensorMap mDispH, mDispM, mGupH, mGupM, mActH, mActM, mDwnH, mDwnM;
    CUtensorMap mHidH, mHidM, mSguH, mSguM, mSactH, mSactM, mSdnH, mSdnM;
    mkmap8(enc, &mDispH, q_disp_h, Hn,  RPAD, 1);
    mkmap8(enc, &mDispM, q_disp_m, Hn,  RPAD, 1);
    mkmap8(enc, &mGupH,  q_gupT_h, Hn,  F2n,  En);
    mkmap8(enc, &mGupM,  q_gupT_m, Hn,  F2n,  En);
    mkmap8(enc, &mActH,  q_act_h,  Fn,  RPAD, 1);
    mkmap8(enc, &mActM,  q_act_m,  Fn,  RPAD, 1);
    mkmap8(enc, &mDwnH,  q_dwnT_h, Fn,  Hn,   En);
    mkmap8(enc, &mDwnM,  q_dwnT_m, Fn,  Hn,   En);
    mkmap8(enc, &mHidH,  q_hid_h,  Hn,  Tn,   1);
    mkmap8(enc, &mHidM,  q_hid_m,  Hn,  Tn,   1);
    mkmap8(enc, &mSguH,  q_sguT_h, Hn,  FS2n, 1);
    mkmap8(enc, &mSguM,  q_sguT_m, Hn,  FS2n, 1);
    mkmap8(enc, &mSactH, q_sact_h, FSn, Tn,   1);
    mkmap8(enc, &mSactM, q_sact_m, FSn, Tn,   1);
    mkmap8(enc, &mSdnH,  q_sdnT_h, FSn, Hn,   1);
    mkmap8(enc, &mSdnM,  q_sdnT_m, FSn, Hn,   1);

    cudaFuncSetAttribute(k_mma8<0,0>, cudaFuncAttributeMaxDynamicSharedMemorySize, GEMM_SMEM);
    cudaFuncSetAttribute(k_mma8<0,1>, cudaFuncAttributeMaxDynamicSharedMemorySize, GEMM_SMEM);
    cudaFuncSetAttribute(k_mma8<1,0>, cudaFuncAttributeMaxDynamicSharedMemorySize, GEMM_SMEM);
    cudaFuncSetAttribute(k_mma8<1,1>, cudaFuncAttributeMaxDynamicSharedMemorySize, GEMM_SMEM);

    // routing + dispatch
    k_init<<<(RPAD + 255) / 256, 256>>>();
    k_router<<<Tn, 128>>>(hs, rw, sgw);
    k_scan<<<1, 1>>>();
    k_scatter<<<64, 256>>>();

    // weight quantization
    k_wmax<<<dim3(256, 1, En), 256>>>(gup, (size_t)Hn * F2n, 0);
    k_wmax<<<dim3(256, 1, En), 256>>>(dwn, (size_t)Fn * Hn, 32);
    k_wmax<<<dim3(256, 1, 1),  256>>>(sgu, (size_t)Hn * FS2n, 64);
    k_wmax<<<dim3(256, 1, 1),  256>>>(sdn, (size_t)FSn * Hn, 65);
    dim3 tb(32, 8);
    k_tquant<1><<<dim3(F2n/32,  Hn/32,  En), tb>>>(gup, (s8*)q_gupT_h, (s8*)q_gupT_m, Hn,  F2n,  Fn,  0);
    k_tquant<0><<<dim3(Hn/32,   Fn/32,  En), tb>>>(dwn, (s8*)q_dwnT_h, (s8*)q_dwnT_m, Fn,  Hn,   0,   32);
    k_tquant<1><<<dim3(FS2n/32, Hn/32,  1 ), tb>>>(sgu, (s8*)q_sguT_h, (s8*)q_sguT_m, Hn,  FS2n, FSn, 64);
    k_tquant<0><<<dim3(Hn/32,   FSn/32, 1 ), tb>>>(sdn, (s8*)q_sdnT_h, (s8*)q_sdnT_m, FSn, Hn,   0,   65);

    // activation quantization + dispatch gather
    k_quant_rows<<<Tn, 256, Hn*4>>>(hs, (s8*)q_hid_h, (s8*)q_hid_m, p_scl_hid, Hn);
    k_gather_q<<<RPAD, 128>>>();

    // expert path: fused gate_up+SwiGLU -> quant -> down
    k_mma8<1,1><<<dim3(F2n/128, MT_E), 256, GEMM_SMEM>>>(mDispH, mDispM, mGupH, mGupM,
                                                         p_act, p_scl_disp, 0, Hn, Fn);
    k_quant_rows<<<RPAD, 256, Fn*4>>>(p_act, (s8*)q_act_h, (s8*)q_act_m, p_scl_act, Fn);
    k_mma8<1,0><<<dim3(Hn/128, MT_E), 256, GEMM_SMEM>>>(mActH, mActM, mDwnH, mDwnM,
                                                        p_eout, p_scl_act, 32, Fn, Hn);

    // shared expert path
    k_mma8<0,1><<<dim3(FS2n/128, Tn/128), 256, GEMM_SMEM>>>(mHidH, mHidM, mSguH, mSguM,
                                                            p_sact, p_scl_hid, 64, Hn, FSn);
    k_quant_rows<<<Tn, 256, FSn*4>>>(p_sact, (s8*)q_sact_h, (s8*)q_sact_m, p_scl_sact, FSn);
    k_mma8<0,0><<<dim3(Hn/128, Tn/128), 256, GEMM_SMEM>>>(mSactH, mSactM, mSdnH, mSdnM,
                                                          p_sout, p_scl_sact, 65, FSn, Hn);

    // combine
    k_combine<<<dim3(Hn/256, Tn), 256>>>(out);
}

// round 5
// speedup vs baseline: 3.4569x; 3.4569x over previous
#include <cuda_runtime.h>
#include <cuda.h>
#include <cuda_fp16.h>
#include <math.h>
#include <stdint.h>

// Problem constants
#define Tn   4096
#define Hn   2048
#define En   32
#define Kn   4
#define Fn   1408
#define F2n  2816
#define FSn  5632
#define FS2n 11264
#define RPAD (Tn*Kn + En*128)     // 20480 expanded rows, expert segs 128-aligned
#define MT_E (RPAD/128)           // 160 expert M-tiles

// ---------------- device scratch ----------------
__device__ __align__(1024) __half g_gupT[(size_t)En*F2n*Hn];   // fp16 weights (hi only)
__device__ __align__(1024) __half g_dwnT[(size_t)En*Hn*Fn];
__device__ __align__(1024) __half g_sguT[(size_t)FS2n*Hn];
__device__ __align__(1024) __half g_sdnT[(size_t)Hn*FSn];
__device__ __align__(1024) __half g_hid_h[(size_t)Tn*Hn];      // activations hi/lo
__device__ __align__(1024) __half g_hid_l[(size_t)Tn*Hn];
__device__ __align__(1024) __half g_disp_h[(size_t)RPAD*Hn];
__device__ __align__(1024) __half g_disp_l[(size_t)RPAD*Hn];
__device__ __align__(1024) __half g_act_h[(size_t)RPAD*Fn];
__device__ __align__(1024) __half g_act_l[(size_t)RPAD*Fn];
__device__ __align__(1024) __half g_sact_h[(size_t)Tn*FSn];
__device__ __align__(1024) __half g_sact_l[(size_t)Tn*FSn];
__device__ float g_eout[(size_t)RPAD * Hn];
__device__ float g_sout[(size_t)Tn * Hn];
__device__ int   g_row_token[RPAD];
__device__ int   g_row_id[Tn*Kn];
__device__ float g_rw[Tn*Kn];
__device__ float g_gate[Tn];
__device__ int   g_cnt[En];
__device__ int   g_off[En+1];
__device__ int   g_pos[Tn*Kn];
__device__ int   g_eidx[Tn*Kn];
__device__ int   g_tile_expert[MT_E];

// ---------------- PTX helpers ----------------
__device__ __forceinline__ uint32_t s2u(const void* p) {
    uint32_t a;
    asm("{ .reg .u64 t; cvta.to.shared.u64 t, %1; cvt.u32.u64 %0, t; }" : "=r"(a) : "l"(p));
    return a;
}
#define MBARRIER_INIT(addr, cnt) \
    asm volatile("mbarrier.init.shared.b64 [%0], %1;" :: "r"((uint32_t)(addr)), "r"((uint32_t)(cnt)) : "memory")
#define MBARRIER_EXPECT_TX(addr, bytes) \
    asm volatile("mbarrier.arrive.expect_tx.shared.b64 _, [%0], %1;" :: "r"((uint32_t)(addr)), "r"((uint32_t)(bytes)) : "memory")
#define MBARRIER_ARRIVE(addr) \
    asm volatile("mbarrier.arrive.shared.b64 _, [%0];" :: "r"((uint32_t)(addr)) : "memory")
#define MBARRIER_WAIT_PARITY(mbar_smem_addr, phase_parity) do { \
    uint32_t _mbar = (uint32_t)(mbar_smem_addr); \
    uint32_t _parity = (uint32_t)(phase_parity); \
    uint32_t _done; \
    asm volatile("{\n\t.reg .pred p;\n\t" \
        "mbarrier.try_wait.parity.acquire.cta.shared::cta.b64 p, [%1], %2;\n\t" \
        "selp.b32 %0, 1, 0, p;\n\t}" \
        : "=r"(_done) : "r"(_mbar), "r"(_parity) : "memory"); \
    if (!_done) { \
        asm volatile("{\n\t.reg .pred P1;\n\t" \
            "WAIT_LOOP_%=:\n\t" \
            "mbarrier.try_wait.parity.acquire.cta.shared::cta.b64 P1, [%0], %1, 0x989680;\n\t" \
            "@P1 bra.uni WAIT_DONE_%=;\n\t" \
            "bra.uni WAIT_LOOP_%=;\n\t" \
            "WAIT_DONE_%=:\n\t}" \
            :: "r"(_mbar), "r"(_parity) : "memory"); \
    } \
} while(0)
#define FENCE_PROXY_ASYNC() asm volatile("fence.proxy.async.shared::cta;" ::: "memory")

__device__ __forceinline__ void tma3(uint32_t dst, const CUtensorMap* m,
                                     int cx, int cy, int cz, uint32_t mbar) {
    asm volatile(
        "cp.async.bulk.tensor.3d.shared::cta.global.tile.mbarrier::complete_tx::bytes "
        "[%0], [%1, {%2, %3, %4}], [%5];"
        :: "r"(dst), "l"(m), "r"(cx), "r"(cy), "r"(cz), "r"(mbar) : "memory");
}
__device__ __forceinline__ void ldsm4(uint32_t* q, uint32_t addr) {
    asm volatile("ldmatrix.sync.aligned.m8n8.x4.shared.b16 {%0,%1,%2,%3}, [%4];"
        : "=r"(q[0]), "=r"(q[1]), "=r"(q[2]), "=r"(q[3]) : "r"(addr));
}
__device__ __forceinline__ void mma_f16(float* c, const uint32_t* a, uint32_t b0, uint32_t b1) {
    asm volatile("mma.sync.aligned.m16n8k16.row.col.f32.f16.f16.f32 "
        "{%0,%1,%2,%3}, {%4,%5,%6,%7}, {%8,%9}, {%0,%1,%2,%3};"
        : "+f"(c[0]), "+f"(c[1]), "+f"(c[2]), "+f"(c[3])
        : "r"(a[0]), "r"(a[1]), "r"(a[2]), "r"(a[3]), "r"(b0), "r"(b1));
}
__device__ __forceinline__ void split2h(float v, __half& h, __half& l) {
    h = __float2half_rn(v);
    l = __float2half_rn(v - __half2float(h));
}

// ---------------- routing ----------------
__global__ void k_init() {
    int i = blockIdx.x * blockDim.x + threadIdx.x;
    if (i < En)   g_cnt[i] = 0;
    if (i < RPAD) g_row_token[i] = -1;
}

__global__ void k_router(const float* __restrict__ hs, const float* __restrict__ rw,
                         const float* __restrict__ gw) {
    __shared__ float sh[Hn];
    __shared__ float slog[En];
    __shared__ float sred[128];
    int t = blockIdx.x;
    const float* hrow = hs + (size_t)t * Hn;
    for (int i = threadIdx.x; i < Hn; i += 128) sh[i] = hrow[i];
    __syncthreads();
    int warp = threadIdx.x >> 5, lane = threadIdx.x & 31;
    #pragma unroll
    for (int eo = 0; eo < 8; eo++) {
        int e = (warp << 3) + eo;
        const float* w = rw + (size_t)e * Hn;
        float acc = 0.f;
        for (int h = lane; h < Hn; h += 32) acc = fmaf(sh[h], w[h], acc);
        #pragma unroll
        for (int o = 16; o; o >>= 1) acc += __shfl_down_sync(0xffffffffu, acc, o);
        if (lane == 0) slog[e] = acc;
    }
    float g = 0.f;
    for (int h = threadIdx.x; h < Hn; h += 128) g = fmaf(sh[h], gw[h], g);
    sred[threadIdx.x] = g;
    __syncthreads();
    for (int s = 64; s; s >>= 1) {
        if (threadIdx.x < s) sred[threadIdx.x] += sred[threadIdx.x + s];
        __syncthreads();
    }
    if (threadIdx.x == 0) {
        g_gate[t] = 1.f / (1.f + expf(-sred[0]));
        float mx = slog[0];
        for (int e = 1; e < En; e++) mx = fmaxf(mx, slog[e]);
        float p[En]; float sum = 0.f;
        for (int e = 0; e < En; e++) { p[e] = expf(slog[e] - mx); sum += p[e]; }
        float inv = 1.f / sum;
        for (int k = 0; k < Kn; k++) {
            int best = 0; float bp = p[0];
            for (int e = 1; e < En; e++) if (p[e] > bp) { bp = p[e]; best = e; }
            int i4 = t * Kn + k;
            g_eidx[i4] = best;
            g_rw[i4]   = bp * inv;
            g_pos[i4]  = atomicAdd(&g_cnt[best], 1);
            p[best] = -1.f;
        }
    }
}

__global__ void k_scan() {
    int o = 0; g_off[0] = 0;
    for (int e = 0; e < En; e++) { o += ((g_cnt[e] + 127) & ~127); g_off[e+1] = o; }
    for (int t = 0; t < MT_E; t++) {
        int r = t * 128, e = -1;
        for (int x = 0; x < En; x++)
            if (r >= g_off[x] && r < g_off[x] + g_cnt[x]) { e = x; break; }
        g_tile_expert[t] = e;
    }
}

__global__ void k_scatter() {
    int i = blockIdx.x * blockDim.x + threadIdx.x;
    if (i >= Tn * Kn) return;
    int e = g_eidx[i];
    int row = g_off[e] + g_pos[i];
    g_row_token[row] = i >> 2;
    g_row_id[i] = row;
}

// ---------------- conversions ----------------
// transpose + fp16 round: W[e][Kd][Nd] fp32 -> WT[e][ndst][Kd] fp16.
// ILV=1 interleaves gate/up columns: dst col = 2*j (gate) / 2*(j-HALF)+1 (up)
template<int ILV>
__global__ void k_thalf(const float* __restrict__ W, __half* __restrict__ o,
                        int Kd, int Nd, int HALF) {
    __shared__ float s[32][33];
    int e = blockIdx.z;
    const float* Wp = W + (size_t)e * Kd * Nd;
    int n0 = blockIdx.x * 32, k0 = blockIdx.y * 32;
    int tx = threadIdx.x, ty = threadIdx.y;
    #pragma unroll
    for (int j = 0; j < 4; j++)
        s[ty + 8*j][tx] = Wp[(size_t)(k0 + ty + 8*j) * Nd + n0 + tx];
    __syncthreads();
    size_t ob = (size_t)e * Nd * Kd;
    #pragma unroll
    for (int j = 0; j < 4; j++) {
        float v = s[tx][ty + 8*j];
        int jsrc = n0 + ty + 8*j;
        int nd = ILV ? (jsrc < HALF ? 2*jsrc : 2*(jsrc - HALF) + 1) : jsrc;
        o[ob + (size_t)nd * Kd + k0 + tx] = __float2half_rn(v);
    }
}

// hidden -> fp16 hi/lo
__global__ void k_split_hid(const float* __restrict__ hs) {
    int row = blockIdx.y;
    int c = blockIdx.x * 256 + threadIdx.x;
    float v = hs[(size_t)row * Hn + c];
    __half h, l; split2h(v, h, l);
    g_hid_h[(size_t)row * Hn + c] = h;
    g_hid_l[(size_t)row * Hn + c] = l;
}

// gather fp16 hidden rows -> dispatched rows (zeros on padding)
__global__ void k_gather_h() {
    int row = blockIdx.x;
    int tid = threadIdx.x;   // 256 threads x 16B = 4096B = Hn halves
    int tok = g_row_token[row];
    int4* dh = (int4*)(g_disp_h + (size_t)row * Hn);
    int4* dl = (int4*)(g_disp_l + (size_t)row * Hn);
    if (tok >= 0) {
        dh[tid] = ((const int4*)(g_hid_h + (size_t)tok * Hn))[tid];
        dl[tid] = ((const int4*)(g_hid_l + (size_t)tok * Hn))[tid];
    } else {
        int4 z = make_int4(0,0,0,0);
        dh[tid] = z; dl[tid] = z;
    }
}

// ---------------- combine ----------------
__global__ void k_combine(float* __restrict__ out) {
    int t = blockIdx.y;
    int h = blockIdx.x * 256 + threadIdx.x;
    float acc = g_gate[t] * g_sout[(size_t)t * Hn + h];
    #pragma unroll
    for (int k = 0; k < Kn; k++) {
        int i4 = t * Kn + k;
        acc = fmaf(g_rw[i4], g_eout[(size_t)g_row_id[i4] * Hn + h], acc);
    }
    out[(size_t)t * Hn + h] = acc;
}

// ---------------- fp16 2-term GEMM: C = (Ahi + Alo) * B^T ----------------
// CTA tile 128x128, K-chunk 64 (SW128 from TMA), 3-stage pipeline.
// 8 warps (2m x 4n), warp tile 64x32, single fp32 accumulator set.
// FUSE=1: interleaved (gate,up) col pairs -> SwiGLU -> split -> fp16 hi/lo out.
#define STAGE_BYTES 49152
#define SMEM_CTRL   1024
#define GEMM_SMEM   (SMEM_CTRL + 3*STAGE_BYTES)

template<int GROUPED, int FUSE>
__global__ void __launch_bounds__(256, 1) k_mma(
    const __grid_constant__ CUtensorMap mAh,
    const __grid_constant__ CUtensorMap mAl,
    const __grid_constant__ CUtensorMap mB,
    float* __restrict__ C, __half* __restrict__ Ch, __half* __restrict__ Cl,
    int Kdim, int NcolsC)
{
    extern __shared__ __align__(1024) char smem[];
    const int mtile = blockIdx.y;
    int eid = 0;
    if (GROUPED) { eid = g_tile_expert[mtile]; if (eid < 0) return; }
    const int m0 = mtile * 128;
    const int n0 = blockIdx.x * 128;
    const int tid  = threadIdx.x;
    const int wid  = tid >> 5;
    const int lane = tid & 31;
    const int mw = (wid >> 2) * 64;
    const int nw = (wid & 3) * 32;
    const uint32_t sb = s2u(smem);
    if (tid == 0) {
        #pragma unroll
        for (int s = 0; s < 3; s++) {
            MBARRIER_INIT(sb + 8*s, 1);
            MBARRIER_INIT(sb + 24 + 8*s, 256);
        }
        FENCE_PROXY_ASYNC();
    }
    __syncthreads();

    const int nch = Kdim >> 6;
    const uint32_t st0 = sb + SMEM_CTRL;

    if (tid == 0) {
        #pragma unroll
        for (int c = 0; c < 3; c++) {
            uint32_t st = st0 + c * STAGE_BYTES;
            int kc = c << 6;
            MBARRIER_EXPECT_TX(sb + 8*c, STAGE_BYTES);
            tma3(st +     0, &mAh, kc, m0, 0,   sb + 8*c);
            tma3(st + 16384, &mAl, kc, m0, 0,   sb + 8*c);
            tma3(st + 32768, &mB,  kc, n0, eid, sb + 8*c);
        }
    }

    float acc[4][4][4];
    #pragma unroll
    for (int i = 0; i < 4; i++)
        #pragma unroll
        for (int j = 0; j < 4; j++)
            #pragma unroll
            for (int q = 0; q < 4; q++) acc[i][j][q] = 0.f;

    const int r15 = lane & 15;
    const int cs  = lane >> 4;

    int s = 0, ph = 0;
    for (int c = 0; c < nch; c++) {
        MBARRIER_WAIT_PARITY(sb + 8*s, ph);
        const uint32_t st = st0 + s * STAGE_BYTES;
        #pragma unroll
        for (int kk = 0; kk < 4; kk++) {
            uint32_t aH[16], aL[16], bb[8];
            #pragma unroll
            for (int mi = 0; mi < 4; mi++) {
                int row = mw + mi * 16 + r15;
                uint32_t off = row * 128 + ((((kk << 1) | cs) ^ (row & 7)) << 4);
                ldsm4(aH + 4*mi, st + off);
                ldsm4(aL + 4*mi, st + 16384 + off);
            }
            #pragma unroll
            for (int nj = 0; nj < 2; nj++) {
                int row = nw + nj * 16 + r15;
                uint32_t off = row * 128 + ((((kk << 1) | cs) ^ (row & 7)) << 4);
                ldsm4(bb + 4*nj, st + 32768 + off);
            }
            #pragma unroll
            for (int mi = 0; mi < 4; mi++) {
                #pragma unroll
                for (int ni = 0; ni < 4; ni++) {
                    int nj = ni >> 1, hf = ni & 1;
                    uint32_t b0 = bb[4*nj + hf], b1 = bb[4*nj + 2 + hf];
                    mma_f16(acc[mi][ni], aH + 4*mi, b0, b1);
                    mma_f16(acc[mi][ni], aL + 4*mi, b0, b1);
                }
            }
        }
        MBARRIER_ARRIVE(sb + 24 + 8*s);
        if (tid == 0 && c + 3 < nch) {
            MBARRIER_WAIT_PARITY(sb + 24 + 8*s, ph);
            int kc = (c + 3) << 6;
            MBARRIER_EXPECT_TX(sb + 8*s, STAGE_BYTES);
            tma3(st +     0, &mAh, kc, m0, 0,   sb + 8*s);
            tma3(st + 16384, &mAl, kc, m0, 0,   sb + 8*s);
            tma3(st + 32768, &mB,  kc, n0, eid, sb + 8*s);
        }
        if (++s == 3) { s = 0; ph ^= 1; }
    }

    // epilogue
    const int er = lane >> 2;
    const int ec = (lane & 3) << 1;
    #pragma unroll
    for (int mi = 0; mi < 4; mi++) {
        int r0 = m0 + mw + mi * 16 + er;
        #pragma unroll
        for (int ni = 0; ni < 4; ni++) {
            float v0 = acc[mi][ni][0], v1 = acc[mi][ni][1];
            float v2 = acc[mi][ni][2], v3 = acc[mi][ni][3];
            if (FUSE) {
                // interleaved: even col = gate, odd = up; thread owns one pair
                int j = (n0 + nw + ni * 8 + ec) >> 1;
                float a0 = v0 / (1.f + expf(-v0)) * v1;
                float a1 = v2 / (1.f + expf(-v2)) * v3;
                __half h0, l0, h1, l1;
                split2h(a0, h0, l0);
                split2h(a1, h1, l1);
                Ch[(size_t)r0 * NcolsC + j] = h0;
                Cl[(size_t)r0 * NcolsC + j] = l0;
                Ch[(size_t)(r0 + 8) * NcolsC + j] = h1;
                Cl[(size_t)(r0 + 8) * NcolsC + j] = l1;
            } else {
                int col = n0 + nw + ni * 8 + ec;
                *(float2*)(C + (size_t)r0 * NcolsC + col)       = make_float2(v0, v1);
                *(float2*)(C + (size_t)(r0 + 8) * NcolsC + col) = make_float2(v2, v3);
            }
        }
    }
}

// ---------------- host launch ----------------
typedef CUresult (*encode_fn_t)(CUtensorMap*, CUtensorMapDataType, cuuint32_t, void*,
                                const cuuint64_t*, const cuuint64_t*, const cuuint32_t*,
                                const cuuint32_t*, CUtensorMapInterleave, CUtensorMapSwizzle,
                                CUtensorMapL2promotion, CUtensorMapFloatOOBfill);

static void mkmap(encode_fn_t enc, CUtensorMap* m, void* ptr,
                  uint64_t d0, uint64_t d1, uint64_t d2) {
    cuuint64_t dims[3] = {d0, d1, d2};
    cuuint64_t str[2]  = {d0 * 2, d0 * d1 * 2};
    cuuint32_t box[3]  = {64, 128, 1};
    cuuint32_t es[3]   = {1, 1, 1};
    enc(m, CU_TENSOR_MAP_DATA_TYPE_FLOAT16, 3, ptr, dims, str, box, es,
        CU_TENSOR_MAP_INTERLEAVE_NONE, CU_TENSOR_MAP_SWIZZLE_128B,
        CU_TENSOR_MAP_L2_PROMOTION_L2_128B, CU_TENSOR_MAP_FLOAT_OOB_FILL_NONE);
}

extern "C" void kernel_launch(void* const* d_in, const int* in_sizes, int n_in,
                              void* d_out, int out_size)
{
    const float* hs  = (const float*)d_in[0];
    const float* rw  = (const float*)d_in[1];
    const float* gup = (const float*)d_in[2];
    const float* dwn = (const float*)d_in[3];
    const float* sgu = (const float*)d_in[4];
    const float* sdn = (const float*)d_in[5];
    const float* sgw = (const float*)d_in[6];
    float* out = (float*)d_out;

    void* fp = nullptr;
    cudaDriverEntryPointQueryResult qr;
    cudaGetDriverEntryPointByVersion("cuTensorMapEncodeTiled", &fp, 12000,
                                     cudaEnableDefault, &qr);
    encode_fn_t enc = (encode_fn_t)fp;

    void *p_gupT, *p_dwnT, *p_sguT, *p_sdnT, *p_hid_h, *p_hid_l, *p_disp_h, *p_disp_l,
         *p_act_h, *p_act_l, *p_sact_h, *p_sact_l;
    float *p_eout, *p_sout;
    cudaGetSymbolAddress(&p_gupT, g_gupT);
    cudaGetSymbolAddress(&p_dwnT, g_dwnT);
    cudaGetSymbolAddress(&p_sguT, g_sguT);
    cudaGetSymbolAddress(&p_sdnT, g_sdnT);
    cudaGetSymbolAddress(&p_hid_h,  g_hid_h);  cudaGetSymbolAddress(&p_hid_l,  g_hid_l);
    cudaGetSymbolAddress(&p_disp_h, g_disp_h); cudaGetSymbolAddress(&p_disp_l, g_disp_l);
    cudaGetSymbolAddress(&p_act_h,  g_act_h);  cudaGetSymbolAddress(&p_act_l,  g_act_l);
    cudaGetSymbolAddress(&p_sact_h, g_sact_h); cudaGetSymbolAddress(&p_sact_l, g_sact_l);
    cudaGetSymbolAddress((void**)&p_eout, g_eout);
    cudaGetSymbolAddress((void**)&p_sout, g_sout);

    CUtensorMap mDispH, mDispL, mGup, mActH, mActL, mDwn;
    CUtensorMap mHidH, mHidL, mSgu, mSactH, mSactL, mSdn;
    mkmap(enc, &mDispH, p_disp_h, Hn,  RPAD, 1);
    mkmap(enc, &mDispL, p_disp_l, Hn,  RPAD, 1);
    mkmap(enc, &mGup,   p_gupT,   Hn,  F2n,  En);
    mkmap(enc, &mActH,  p_act_h,  Fn,  RPAD, 1);
    mkmap(enc, &mActL,  p_act_l,  Fn,  RPAD, 1);
    mkmap(enc, &mDwn,   p_dwnT,   Fn,  Hn,   En);
    mkmap(enc, &mHidH,  p_hid_h,  Hn,  Tn,   1);
    mkmap(enc, &mHidL,  p_hid_l,  Hn,  Tn,   1);
    mkmap(enc, &mSgu,   p_sguT,   Hn,  FS2n, 1);
    mkmap(enc, &mSactH, p_sact_h, FSn, Tn,   1);
    mkmap(enc, &mSactL, p_sact_l, FSn, Tn,   1);
    mkmap(enc, &mSdn,   p_sdnT,   FSn, Hn,   1);

    cudaFuncSetAttribute(k_mma<0,0>, cudaFuncAttributeMaxDynamicSharedMemorySize, GEMM_SMEM);
    cudaFuncSetAttribute(k_mma<0,1>, cudaFuncAttributeMaxDynamicSharedMemorySize, GEMM_SMEM);
    cudaFuncSetAttribute(k_mma<1,0>, cudaFuncAttributeMaxDynamicSharedMemorySize, GEMM_SMEM);
    cudaFuncSetAttribute(k_mma<1,1>, cudaFuncAttributeMaxDynamicSharedMemorySize, GEMM_SMEM);

    // routing + dispatch
    k_init<<<(RPAD + 255) / 256, 256>>>();
    k_router<<<Tn, 128>>>(hs, rw, sgw);
    k_scan<<<1, 1>>>();
    k_scatter<<<64, 256>>>();

    // conversions (weights: transpose + fp16; gate_up matrices interleaved)
    dim3 tb(32, 8);
    k_thalf<1><<<dim3(F2n/32,  Hn/32,  En), tb>>>(gup, (__half*)p_gupT, Hn,  F2n,  Fn);
    k_thalf<0><<<dim3(Hn/32,   Fn/32,  En), tb>>>(dwn, (__half*)p_dwnT, Fn,  Hn,   0);
    k_thalf<1><<<dim3(FS2n/32, Hn/32,  1 ), tb>>>(sgu, (__half*)p_sguT, Hn,  FS2n, FSn);
    k_thalf<0><<<dim3(Hn/32,   FSn/32, 1 ), tb>>>(sdn, (__half*)p_sdnT, FSn, Hn,   0);
    k_split_hid<<<dim3(Hn/256, Tn), 256>>>(hs);
    k_gather_h<<<RPAD, 256>>>();

    // expert path: fused gate_up+SwiGLU(+split) -> down
    k_mma<1,1><<<dim3(F2n/128, MT_E), 256, GEMM_SMEM>>>(mDispH, mDispL, mGup,
        nullptr, (__half*)p_act_h, (__half*)p_act_l, Hn, Fn);
    k_mma<1,0><<<dim3(Hn/128, MT_E), 256, GEMM_SMEM>>>(mActH, mActL, mDwn,
        p_eout, nullptr, nullptr, Fn, Hn);

    // shared expert path
    k_mma<0,1><<<dim3(FS2n/128, Tn/128), 256, GEMM_SMEM>>>(mHidH, mHidL, mSgu,
        nullptr, (__half*)p_sact_h, (__half*)p_sact_l, Hn, FSn);
    k_mma<0,0><<<dim3(Hn/128, Tn/128), 256, GEMM_SMEM>>>(mSactH, mSactL, mSdn,
        p_sout, nullptr, nullptr, FSn, Hn);

    // combine
    k_combine<<<dim3(Hn/256, Tn), 256>>>(out);
}

// round 6
// speedup vs baseline: 5.7327x; 1.6583x over previous
#include <cuda_runtime.h>
#include <cuda.h>
#include <cuda_fp16.h>
#include <math.h>
#include <stdint.h>

// Problem constants
#define Tn   4096
#define Hn   2048
#define En   32
#define Kn   4
#define Fn   1408
#define F2n  2816
#define FSn  5632
#define FS2n 11264
#define RPAD (Tn*Kn + En*128)     // 20480 expanded rows, expert segs 128-aligned
#define MT_E (RPAD/128)           // 160 expert M-tiles

// ---------------- device scratch ----------------
__device__ __align__(1024) __half g_gupT[(size_t)En*F2n*Hn];   // fp16 weights, transposed
__device__ __align__(1024) __half g_dwnT[(size_t)En*Hn*Fn];
__device__ __align__(1024) __half g_sguT[(size_t)FS2n*Hn];
__device__ __align__(1024) __half g_sdnT[(size_t)Hn*FSn];
__device__ __align__(1024) __half g_hid[(size_t)Tn*Hn];        // fp16 activations
__device__ __align__(1024) __half g_disp[(size_t)RPAD*Hn];
__device__ __align__(1024) __half g_act[(size_t)RPAD*Fn];
__device__ __align__(1024) __half g_sact[(size_t)Tn*FSn];
__device__ float g_eout[(size_t)RPAD * Hn];
__device__ float g_sout[(size_t)Tn * Hn];
__device__ int   g_row_token[RPAD];
__device__ int   g_row_id[Tn*Kn];
__device__ float g_rw[Tn*Kn];
__device__ float g_gate[Tn];
__device__ int   g_cnt[En];
__device__ int   g_off[En+1];
__device__ int   g_pos[Tn*Kn];
__device__ int   g_eidx[Tn*Kn];
__device__ int   g_tile_expert[MT_E];

// ---------------- PTX helpers ----------------
__device__ __forceinline__ uint32_t s2u(const void* p) {
    uint32_t a;
    asm("{ .reg .u64 t; cvta.to.shared.u64 t, %1; cvt.u32.u64 %0, t; }" : "=r"(a) : "l"(p));
    return a;
}
#define MBARRIER_INIT(addr, cnt) \
    asm volatile("mbarrier.init.shared.b64 [%0], %1;" :: "r"((uint32_t)(addr)), "r"((uint32_t)(cnt)) : "memory")
#define MBARRIER_EXPECT_TX(addr, bytes) \
    asm volatile("mbarrier.arrive.expect_tx.shared.b64 _, [%0], %1;" :: "r"((uint32_t)(addr)), "r"((uint32_t)(bytes)) : "memory")
#define MBARRIER_ARRIVE(addr) \
    asm volatile("mbarrier.arrive.shared.b64 _, [%0];" :: "r"((uint32_t)(addr)) : "memory")
#define MBARRIER_WAIT_PARITY(mbar_smem_addr, phase_parity) do { \
    uint32_t _mbar = (uint32_t)(mbar_smem_addr); \
    uint32_t _parity = (uint32_t)(phase_parity); \
    uint32_t _done; \
    asm volatile("{\n\t.reg .pred p;\n\t" \
        "mbarrier.try_wait.parity.acquire.cta.shared::cta.b64 p, [%1], %2;\n\t" \
        "selp.b32 %0, 1, 0, p;\n\t}" \
        : "=r"(_done) : "r"(_mbar), "r"(_parity) : "memory"); \
    if (!_done) { \
        asm volatile("{\n\t.reg .pred P1;\n\t" \
            "WAIT_LOOP_%=:\n\t" \
            "mbarrier.try_wait.parity.acquire.cta.shared::cta.b64 P1, [%0], %1, 0x989680;\n\t" \
            "@P1 bra.uni WAIT_DONE_%=;\n\t" \
            "bra.uni WAIT_LOOP_%=;\n\t" \
            "WAIT_DONE_%=:\n\t}" \
            :: "r"(_mbar), "r"(_parity) : "memory"); \
    } \
} while(0)
#define FENCE_PROXY_ASYNC() asm volatile("fence.proxy.async.shared::cta;" ::: "memory")

__device__ __forceinline__ void tma3(uint32_t dst, const CUtensorMap* m,
                                     int cx, int cy, int cz, uint32_t mbar) {
    asm volatile(
        "cp.async.bulk.tensor.3d.shared::cta.global.tile.mbarrier::complete_tx::bytes "
        "[%0], [%1, {%2, %3, %4}], [%5];"
        :: "r"(dst), "l"(m), "r"(cx), "r"(cy), "r"(cz), "r"(mbar) : "memory");
}
__device__ __forceinline__ void ldsm4(uint32_t* q, uint32_t addr) {
    asm volatile("ldmatrix.sync.aligned.m8n8.x4.shared.b16 {%0,%1,%2,%3}, [%4];"
        : "=r"(q[0]), "=r"(q[1]), "=r"(q[2]), "=r"(q[3]) : "r"(addr));
}
__device__ __forceinline__ void mma_f16(float* c, const uint32_t* a, uint32_t b0, uint32_t b1) {
    asm volatile("mma.sync.aligned.m16n8k16.row.col.f32.f16.f16.f32 "
        "{%0,%1,%2,%3}, {%4,%5,%6,%7}, {%8,%9}, {%0,%1,%2,%3};"
        : "+f"(c[0]), "+f"(c[1]), "+f"(c[2]), "+f"(c[3])
        : "r"(a[0]), "r"(a[1]), "r"(a[2]), "r"(a[3]), "r"(b0), "r"(b1));
}

// ---------------- routing ----------------
__global__ void k_init() {
    int i = blockIdx.x * blockDim.x + threadIdx.x;
    if (i < En)   g_cnt[i] = 0;
    if (i < RPAD) g_row_token[i] = -1;
}

__global__ void k_router(const float* __restrict__ hs, const float* __restrict__ rw,
                         const float* __restrict__ gw) {
    __shared__ float sh[Hn];
    __shared__ float slog[En];
    __shared__ float sred[128];
    int t = blockIdx.x;
    const float* hrow = hs + (size_t)t * Hn;
    for (int i = threadIdx.x; i < Hn; i += 128) sh[i] = hrow[i];
    __syncthreads();
    int warp = threadIdx.x >> 5, lane = threadIdx.x & 31;
    #pragma unroll
    for (int eo = 0; eo < 8; eo++) {
        int e = (warp << 3) + eo;
        const float* w = rw + (size_t)e * Hn;
        float acc = 0.f;
        for (int h = lane; h < Hn; h += 32) acc = fmaf(sh[h], w[h], acc);
        #pragma unroll
        for (int o = 16; o; o >>= 1) acc += __shfl_down_sync(0xffffffffu, acc, o);
        if (lane == 0) slog[e] = acc;
    }
    float g = 0.f;
    for (int h = threadIdx.x; h < Hn; h += 128) g = fmaf(sh[h], gw[h], g);
    sred[threadIdx.x] = g;
    __syncthreads();
    for (int s = 64; s; s >>= 1) {
        if (threadIdx.x < s) sred[threadIdx.x] += sred[threadIdx.x + s];
        __syncthreads();
    }
    if (threadIdx.x == 0) {
        g_gate[t] = 1.f / (1.f + expf(-sred[0]));
        float mx = slog[0];
        for (int e = 1; e < En; e++) mx = fmaxf(mx, slog[e]);
        float p[En]; float sum = 0.f;
        for (int e = 0; e < En; e++) { p[e] = expf(slog[e] - mx); sum += p[e]; }
        float inv = 1.f / sum;
        for (int k = 0; k < Kn; k++) {
            int best = 0; float bp = p[0];
            for (int e = 1; e < En; e++) if (p[e] > bp) { bp = p[e]; best = e; }
            int i4 = t * Kn + k;
            g_eidx[i4] = best;
            g_rw[i4]   = bp * inv;
            g_pos[i4]  = atomicAdd(&g_cnt[best], 1);
            p[best] = -1.f;
        }
    }
}

__global__ void k_scan() {
    int o = 0; g_off[0] = 0;
    for (int e = 0; e < En; e++) { o += ((g_cnt[e] + 127) & ~127); g_off[e+1] = o; }
    for (int t = 0; t < MT_E; t++) {
        int r = t * 128, e = -1;
        for (int x = 0; x < En; x++)
            if (r >= g_off[x] && r < g_off[x] + g_cnt[x]) { e = x; break; }
        g_tile_expert[t] = e;
    }
}

__global__ void k_scatter() {
    int i = blockIdx.x * blockDim.x + threadIdx.x;
    if (i >= Tn * Kn) return;
    int e = g_eidx[i];
    int row = g_off[e] + g_pos[i];
    g_row_token[row] = i >> 2;
    g_row_id[i] = row;
}

// ---------------- conversions ----------------
// transpose + fp16 round: W[e][Kd][Nd] fp32 -> WT[e][ndst][Kd] fp16.
// ILV=1 interleaves gate/up columns: dst col = 2*j (gate) / 2*(j-HALF)+1 (up)
template<int ILV>
__global__ void k_thalf(const float* __restrict__ W, __half* __restrict__ o,
                        int Kd, int Nd, int HALF) {
    __shared__ float s[32][33];
    int e = blockIdx.z;
    const float* Wp = W + (size_t)e * Kd * Nd;
    int n0 = blockIdx.x * 32, k0 = blockIdx.y * 32;
    int tx = threadIdx.x, ty = threadIdx.y;
    #pragma unroll
    for (int j = 0; j < 4; j++)
        s[ty + 8*j][tx] = Wp[(size_t)(k0 + ty + 8*j) * Nd + n0 + tx];
    __syncthreads();
    size_t ob = (size_t)e * Nd * Kd;
    #pragma unroll
    for (int j = 0; j < 4; j++) {
        float v = s[tx][ty + 8*j];
        int jsrc = n0 + ty + 8*j;
        int nd = ILV ? (jsrc < HALF ? 2*jsrc : 2*(jsrc - HALF) + 1) : jsrc;
        o[ob + (size_t)nd * Kd + k0 + tx] = __float2half_rn(v);
    }
}

// hidden -> fp16
__global__ void k_half_hid(const float* __restrict__ hs) {
    int row = blockIdx.y;
    int c = blockIdx.x * 256 + threadIdx.x;
    g_hid[(size_t)row * Hn + c] = __float2half_rn(hs[(size_t)row * Hn + c]);
}

// gather fp16 hidden rows -> dispatched rows (zeros on padding)
__global__ void k_gather_h() {
    int row = blockIdx.x;
    int tid = threadIdx.x;   // 256 threads x 16B = 4096B = Hn halves
    int tok = g_row_token[row];
    int4* d = (int4*)(g_disp + (size_t)row * Hn);
    if (tok >= 0) d[tid] = ((const int4*)(g_hid + (size_t)tok * Hn))[tid];
    else          d[tid] = make_int4(0,0,0,0);
}

// ---------------- combine ----------------
__global__ void k_combine(float* __restrict__ out) {
    int t = blockIdx.y;
    int h = blockIdx.x * 256 + threadIdx.x;
    float acc = g_gate[t] * g_sout[(size_t)t * Hn + h];
    #pragma unroll
    for (int k = 0; k < Kn; k++) {
        int i4 = t * Kn + k;
        acc = fmaf(g_rw[i4], g_eout[(size_t)g_row_id[i4] * Hn + h], acc);
    }
    out[(size_t)t * Hn + h] = acc;
}

// ---------------- single-term fp16 GEMM: C = A * B^T ----------------
// CTA tile 128x128, K-chunk 64 (SW128 from TMA), 4-stage pipeline (32KB/stage).
// 8 warps (2m x 4n), warp tile 64x32, fp32 accumulators.
// FUSE=1: interleaved (gate,up) col pairs -> SwiGLU -> fp16 out.
#define STAGE_BYTES 32768
#define SMEM_CTRL   1024
#define NSTAGE      4
#define GEMM_SMEM   (SMEM_CTRL + NSTAGE*STAGE_BYTES)

template<int GROUPED, int FUSE>
__global__ void __launch_bounds__(256, 1) k_mma(
    const __grid_constant__ CUtensorMap mA,
    const __grid_constant__ CUtensorMap mB,
    float* __restrict__ C, __half* __restrict__ Ch,
    int Kdim, int NcolsC)
{
    extern __shared__ __align__(1024) char smem[];
    const int mtile = blockIdx.y;
    int eid = 0;
    if (GROUPED) { eid = g_tile_expert[mtile]; if (eid < 0) return; }
    const int m0 = mtile * 128;
    const int n0 = blockIdx.x * 128;
    const int tid  = threadIdx.x;
    const int wid  = tid >> 5;
    const int lane = tid & 31;
    const int mw = (wid >> 2) * 64;
    const int nw = (wid & 3) * 32;
    const uint32_t sb = s2u(smem);
    // full barriers at sb + 8*s, free barriers at sb + 64 + 8*s
    if (tid == 0) {
        #pragma unroll
        for (int s = 0; s < NSTAGE; s++) {
            MBARRIER_INIT(sb + 8*s, 1);
            MBARRIER_INIT(sb + 64 + 8*s, 256);
        }
        FENCE_PROXY_ASYNC();
    }
    __syncthreads();

    const int nch = Kdim >> 6;
    const uint32_t st0 = sb + SMEM_CTRL;

    if (tid == 0) {
        #pragma unroll
        for (int c = 0; c < NSTAGE; c++) {
            if (c >= nch) break;
            uint32_t st = st0 + c * STAGE_BYTES;
            int kc = c << 6;
            MBARRIER_EXPECT_TX(sb + 8*c, STAGE_BYTES);
            tma3(st +     0, &mA, kc, m0, 0,   sb + 8*c);
            tma3(st + 16384, &mB, kc, n0, eid, sb + 8*c);
        }
    }

    float acc[4][4][4];
    #pragma unroll
    for (int i = 0; i < 4; i++)
        #pragma unroll
        for (int j = 0; j < 4; j++)
            #pragma unroll
            for (int q = 0; q < 4; q++) acc[i][j][q] = 0.f;

    const int r15 = lane & 15;
    const int cs  = lane >> 4;

    for (int c = 0; c < nch; c++) {
        int s = c & (NSTAGE - 1);
        int ph = (c >> 2) & 1;
        MBARRIER_WAIT_PARITY(sb + 8*s, ph);
        const uint32_t st = st0 + s * STAGE_BYTES;
        #pragma unroll
        for (int kk = 0; kk < 4; kk++) {
            uint32_t aa[16], bb[8];
            #pragma unroll
            for (int mi = 0; mi < 4; mi++) {
                int row = mw + mi * 16 + r15;
                uint32_t off = row * 128 + ((((kk << 1) | cs) ^ (row & 7)) << 4);
                ldsm4(aa + 4*mi, st + off);
            }
            #pragma unroll
            for (int nj = 0; nj < 2; nj++) {
                int row = nw + nj * 16 + r15;
                uint32_t off = row * 128 + ((((kk << 1) | cs) ^ (row & 7)) << 4);
                ldsm4(bb + 4*nj, st + 16384 + off);
            }
            #pragma unroll
            for (int mi = 0; mi < 4; mi++) {
                #pragma unroll
                for (int ni = 0; ni < 4; ni++) {
                    int nj = ni >> 1, hf = ni & 1;
                    mma_f16(acc[mi][ni], aa + 4*mi, bb[4*nj + hf], bb[4*nj + 2 + hf]);
                }
            }
        }
        MBARRIER_ARRIVE(sb + 64 + 8*s);
        if (tid == 0 && c + NSTAGE < nch) {
            MBARRIER_WAIT_PARITY(sb + 64 + 8*s, ph);
            int kc = (c + NSTAGE) << 6;
            MBARRIER_EXPECT_TX(sb + 8*s, STAGE_BYTES);
            tma3(st +     0, &mA, kc, m0, 0,   sb + 8*s);
            tma3(st + 16384, &mB, kc, n0, eid, sb + 8*s);
        }
    }

    // epilogue
    const int er = lane >> 2;
    const int ec = (lane & 3) << 1;
    #pragma unroll
    for (int mi = 0; mi < 4; mi++) {
        int r0 = m0 + mw + mi * 16 + er;
        #pragma unroll
        for (int ni = 0; ni < 4; ni++) {
            float v0 = acc[mi][ni][0], v1 = acc[mi][ni][1];
            float v2 = acc[mi][ni][2], v3 = acc[mi][ni][3];
            if (FUSE) {
                // interleaved: even col = gate, odd = up; thread owns one pair
                int j = (n0 + nw + ni * 8 + ec) >> 1;
                float a0 = v0 / (1.f + expf(-v0)) * v1;
                float a1 = v2 / (1.f + expf(-v2)) * v3;
                Ch[(size_t)r0 * NcolsC + j]       = __float2half_rn(a0);
                Ch[(size_t)(r0 + 8) * NcolsC + j] = __float2half_rn(a1);
            } else {
                int col = n0 + nw + ni * 8 + ec;
                *(float2*)(C + (size_t)r0 * NcolsC + col)       = make_float2(v0, v1);
                *(float2*)(C + (size_t)(r0 + 8) * NcolsC + col) = make_float2(v2, v3);
            }
        }
    }
}

// ---------------- host launch ----------------
typedef CUresult (*encode_fn_t)(CUtensorMap*, CUtensorMapDataType, cuuint32_t, void*,
                                const cuuint64_t*, const cuuint64_t*, const cuuint32_t*,
                                const cuuint32_t*, CUtensorMapInterleave, CUtensorMapSwizzle,
                                CUtensorMapL2promotion, CUtensorMapFloatOOBfill);

static void mkmap(encode_fn_t enc, CUtensorMap* m, void* ptr,
                  uint64_t d0, uint64_t d1, uint64_t d2) {
    cuuint64_t dims[3] = {d0, d1, d2};
    cuuint64_t str[2]  = {d0 * 2, d0 * d1 * 2};
    cuuint32_t box[3]  = {64, 128, 1};
    cuuint32_t es[3]   = {1, 1, 1};
    enc(m, CU_TENSOR_MAP_DATA_TYPE_FLOAT16, 3, ptr, dims, str, box, es,
        CU_TENSOR_MAP_INTERLEAVE_NONE, CU_TENSOR_MAP_SWIZZLE_128B,
        CU_TENSOR_MAP_L2_PROMOTION_L2_128B, CU_TENSOR_MAP_FLOAT_OOB_FILL_NONE);
}

extern "C" void kernel_launch(void* const* d_in, const int* in_sizes, int n_in,
                              void* d_out, int out_size)
{
    const float* hs  = (const float*)d_in[0];
    const float* rw  = (const float*)d_in[1];
    const float* gup = (const float*)d_in[2];
    const float* dwn = (const float*)d_in[3];
    const float* sgu = (const float*)d_in[4];
    const float* sdn = (const float*)d_in[5];
    const float* sgw = (const float*)d_in[6];
    float* out = (float*)d_out;

    void* fp = nullptr;
    cudaDriverEntryPointQueryResult qr;
    cudaGetDriverEntryPointByVersion("cuTensorMapEncodeTiled", &fp, 12000,
                                     cudaEnableDefault, &qr);
    encode_fn_t enc = (encode_fn_t)fp;

    void *p_gupT, *p_dwnT, *p_sguT, *p_sdnT, *p_hid, *p_disp, *p_act, *p_sact;
    float *p_eout, *p_sout;
    cudaGetSymbolAddress(&p_gupT, g_gupT);
    cudaGetSymbolAddress(&p_dwnT, g_dwnT);
    cudaGetSymbolAddress(&p_sguT, g_sguT);
    cudaGetSymbolAddress(&p_sdnT, g_sdnT);
    cudaGetSymbolAddress(&p_hid,  g_hid);
    cudaGetSymbolAddress(&p_disp, g_disp);
    cudaGetSymbolAddress(&p_act,  g_act);
    cudaGetSymbolAddress(&p_sact, g_sact);
    cudaGetSymbolAddress((void**)&p_eout, g_eout);
    cudaGetSymbolAddress((void**)&p_sout, g_sout);

    CUtensorMap mDisp, mGup, mAct, mDwn, mHid, mSgu, mSact, mSdn;
    mkmap(enc, &mDisp, p_disp, Hn,  RPAD, 1);
    mkmap(enc, &mGup,  p_gupT, Hn,  F2n,  En);
    mkmap(enc, &mAct,  p_act,  Fn,  RPAD, 1);
    mkmap(enc, &mDwn,  p_dwnT, Fn,  Hn,   En);
    mkmap(enc, &mHid,  p_hid,  Hn,  Tn,   1);
    mkmap(enc, &mSgu,  p_sguT, Hn,  FS2n, 1);
    mkmap(enc, &mSact, p_sact, FSn, Tn,   1);
    mkmap(enc, &mSdn,  p_sdnT, FSn, Hn,   1);

    cudaFuncSetAttribute(k_mma<0,0>, cudaFuncAttributeMaxDynamicSharedMemorySize, GEMM_SMEM);
    cudaFuncSetAttribute(k_mma<0,1>, cudaFuncAttributeMaxDynamicSharedMemorySize, GEMM_SMEM);
    cudaFuncSetAttribute(k_mma<1,0>, cudaFuncAttributeMaxDynamicSharedMemorySize, GEMM_SMEM);
    cudaFuncSetAttribute(k_mma<1,1>, cudaFuncAttributeMaxDynamicSharedMemorySize, GEMM_SMEM);

    // routing + dispatch
    k_init<<<(RPAD + 255) / 256, 256>>>();
    k_router<<<Tn, 128>>>(hs, rw, sgw);
    k_scan<<<1, 1>>>();
    k_scatter<<<64, 256>>>();

    // conversions (weights: transpose + fp16; gate_up matrices interleaved)
    dim3 tb(32, 8);
    k_thalf<1><<<dim3(F2n/32,  Hn/32,  En), tb>>>(gup, (__half*)p_gupT, Hn,  F2n,  Fn);
    k_thalf<0><<<dim3(Hn/32,   Fn/32,  En), tb>>>(dwn, (__half*)p_dwnT, Fn,  Hn,   0);
    k_thalf<1><<<dim3(FS2n/32, Hn/32,  1 ), tb>>>(sgu, (__half*)p_sguT, Hn,  FS2n, FSn);
    k_thalf<0><<<dim3(Hn/32,   FSn/32, 1 ), tb>>>(sdn, (__half*)p_sdnT, FSn, Hn,   0);
    k_half_hid<<<dim3(Hn/256, Tn), 256>>>(hs);
    k_gather_h<<<RPAD, 256>>>();

    // expert path: fused gate_up+SwiGLU -> down
    k_mma<1,1><<<dim3(F2n/128, MT_E), 256, GEMM_SMEM>>>(mDisp, mGup,
        nullptr, (__half*)p_act, Hn, Fn);
    k_mma<1,0><<<dim3(Hn/128, MT_E), 256, GEMM_SMEM>>>(mAct, mDwn,
        p_eout, nullptr, Fn, Hn);

    // shared expert path
    k_mma<0,1><<<dim3(FS2n/128, Tn/128), 256, GEMM_SMEM>>>(mHid, mSgu,
        nullptr, (__half*)p_sact, Hn, FSn);
    k_mma<0,0><<<dim3(Hn/128, Tn/128), 256, GEMM_SMEM>>>(mSact, mSdn,
        p_sout, nullptr, FSn, Hn);

    // combine
    k_combine<<<dim3(Hn/256, Tn), 256>>>(out);
}

// round 7
// speedup vs baseline: 6.4740x; 1.1293x over previous
#include <cuda_runtime.h>
#include <cuda.h>
#include <cuda_fp16.h>
#include <math.h>
#include <stdint.h>

// Problem constants
#define Tn   4096
#define Hn   2048
#define En   32
#define Kn   4
#define Fn   1408
#define F2n  2816
#define FSn  5632
#define FS2n 11264
#define RPAD (Tn*Kn + En*128)     // 20480 expanded rows, expert segs 128-aligned
#define MT_E (RPAD/128)           // 160 expert M-tiles

// ---------------- device scratch ----------------
__device__ __align__(1024) __half g_gupT[(size_t)En*F2n*Hn];   // fp16 weights, transposed
__device__ __align__(1024) __half g_dwnT[(size_t)En*Hn*Fn];
__device__ __align__(1024) __half g_sguT[(size_t)FS2n*Hn];
__device__ __align__(1024) __half g_sdnT[(size_t)Hn*FSn];
__device__ __align__(1024) __half g_hid[(size_t)Tn*Hn];        // fp16 activations
__device__ __align__(1024) __half g_disp[(size_t)RPAD*Hn];
__device__ __align__(1024) __half g_act[(size_t)RPAD*Fn];
__device__ __align__(1024) __half g_sact[(size_t)Tn*FSn];
__device__ int   g_row_token[RPAD];
__device__ float g_row_rw[RPAD];
__device__ float g_rw[Tn*Kn];
__device__ float g_gate[Tn];
__device__ int   g_cnt[En];
__device__ int   g_off[En+1];
__device__ int   g_pos[Tn*Kn];
__device__ int   g_eidx[Tn*Kn];
__device__ int   g_tile_expert[MT_E];

// ---------------- PTX helpers ----------------
__device__ __forceinline__ uint32_t s2u(const void* p) {
    uint32_t a;
    asm("{ .reg .u64 t; cvta.to.shared.u64 t, %1; cvt.u32.u64 %0, t; }" : "=r"(a) : "l"(p));
    return a;
}
#define MBARRIER_INIT(addr, cnt) \
    asm volatile("mbarrier.init.shared.b64 [%0], %1;" :: "r"((uint32_t)(addr)), "r"((uint32_t)(cnt)) : "memory")
#define MBARRIER_EXPECT_TX(addr, bytes) \
    asm volatile("mbarrier.arrive.expect_tx.shared.b64 _, [%0], %1;" :: "r"((uint32_t)(addr)), "r"((uint32_t)(bytes)) : "memory")
#define MBARRIER_ARRIVE(addr) \
    asm volatile("mbarrier.arrive.shared.b64 _, [%0];" :: "r"((uint32_t)(addr)) : "memory")
#define MBARRIER_WAIT_PARITY(mbar_smem_addr, phase_parity) do { \
    uint32_t _mbar = (uint32_t)(mbar_smem_addr); \
    uint32_t _parity = (uint32_t)(phase_parity); \
    uint32_t _done; \
    asm volatile("{\n\t.reg .pred p;\n\t" \
        "mbarrier.try_wait.parity.acquire.cta.shared::cta.b64 p, [%1], %2;\n\t" \
        "selp.b32 %0, 1, 0, p;\n\t}" \
        : "=r"(_done) : "r"(_mbar), "r"(_parity) : "memory"); \
    if (!_done) { \
        asm volatile("{\n\t.reg .pred P1;\n\t" \
            "WAIT_LOOP_%=:\n\t" \
            "mbarrier.try_wait.parity.acquire.cta.shared::cta.b64 P1, [%0], %1, 0x989680;\n\t" \
            "@P1 bra.uni WAIT_DONE_%=;\n\t" \
            "bra.uni WAIT_LOOP_%=;\n\t" \
            "WAIT_DONE_%=:\n\t}" \
            :: "r"(_mbar), "r"(_parity) : "memory"); \
    } \
} while(0)
#define FENCE_PROXY_ASYNC() asm volatile("fence.proxy.async.shared::cta;" ::: "memory")

__device__ __forceinline__ void tma3(uint32_t dst, const CUtensorMap* m,
                                     int cx, int cy, int cz, uint32_t mbar) {
    asm volatile(
        "cp.async.bulk.tensor.3d.shared::cta.global.tile.mbarrier::complete_tx::bytes "
        "[%0], [%1, {%2, %3, %4}], [%5];"
        :: "r"(dst), "l"(m), "r"(cx), "r"(cy), "r"(cz), "r"(mbar) : "memory");
}
__device__ __forceinline__ void ldsm4(uint32_t* q, uint32_t addr) {
    asm volatile("ldmatrix.sync.aligned.m8n8.x4.shared.b16 {%0,%1,%2,%3}, [%4];"
        : "=r"(q[0]), "=r"(q[1]), "=r"(q[2]), "=r"(q[3]) : "r"(addr));
}
__device__ __forceinline__ void mma_f16(float* c, const uint32_t* a, uint32_t b0, uint32_t b1) {
    asm volatile("mma.sync.aligned.m16n8k16.row.col.f32.f16.f16.f32 "
        "{%0,%1,%2,%3}, {%4,%5,%6,%7}, {%8,%9}, {%0,%1,%2,%3};"
        : "+f"(c[0]), "+f"(c[1]), "+f"(c[2]), "+f"(c[3])
        : "r"(a[0]), "r"(a[1]), "r"(a[2]), "r"(a[3]), "r"(b0), "r"(b1));
}

// ---------------- routing ----------------
__global__ void k_init() {
    int i = blockIdx.x * blockDim.x + threadIdx.x;
    if (i < En)   g_cnt[i] = 0;
    if (i < RPAD) g_row_token[i] = -1;
}

__global__ void k_zero(float* __restrict__ out) {
    size_t i = (size_t)blockIdx.x * blockDim.x + threadIdx.x;
    ((float4*)out)[i] = make_float4(0.f, 0.f, 0.f, 0.f);
}

__global__ void k_router(const float* __restrict__ hs, const float* __restrict__ rw,
                         const float* __restrict__ gw) {
    __shared__ float sh[Hn];
    __shared__ float slog[En];
    __shared__ float sred[128];
    int t = blockIdx.x;
    const float* hrow = hs + (size_t)t * Hn;
    for (int i = threadIdx.x; i < Hn; i += 128) sh[i] = hrow[i];
    __syncthreads();
    int warp = threadIdx.x >> 5, lane = threadIdx.x & 31;
    #pragma unroll
    for (int eo = 0; eo < 8; eo++) {
        int e = (warp << 3) + eo;
        const float* w = rw + (size_t)e * Hn;
        float acc = 0.f;
        for (int h = lane; h < Hn; h += 32) acc = fmaf(sh[h], w[h], acc);
        #pragma unroll
        for (int o = 16; o; o >>= 1) acc += __shfl_down_sync(0xffffffffu, acc, o);
        if (lane == 0) slog[e] = acc;
    }
    float g = 0.f;
    for (int h = threadIdx.x; h < Hn; h += 128) g = fmaf(sh[h], gw[h], g);
    sred[threadIdx.x] = g;
    __syncthreads();
    for (int s = 64; s; s >>= 1) {
        if (threadIdx.x < s) sred[threadIdx.x] += sred[threadIdx.x + s];
        __syncthreads();
    }
    if (threadIdx.x == 0) {
        g_gate[t] = 1.f / (1.f + expf(-sred[0]));
        float mx = slog[0];
        for (int e = 1; e < En; e++) mx = fmaxf(mx, slog[e]);
        float p[En]; float sum = 0.f;
        for (int e = 0; e < En; e++) { p[e] = expf(slog[e] - mx); sum += p[e]; }
        float inv = 1.f / sum;
        for (int k = 0; k < Kn; k++) {
            int best = 0; float bp = p[0];
            for (int e = 1; e < En; e++) if (p[e] > bp) { bp = p[e]; best = e; }
            int i4 = t * Kn + k;
            g_eidx[i4] = best;
            g_rw[i4]   = bp * inv;
            g_pos[i4]  = atomicAdd(&g_cnt[best], 1);
            p[best] = -1.f;
        }
    }
}

__global__ void k_scan() {
    int o = 0; g_off[0] = 0;
    for (int e = 0; e < En; e++) { o += ((g_cnt[e] + 127) & ~127); g_off[e+1] = o; }
    for (int t = 0; t < MT_E; t++) {
        int r = t * 128, e = -1;
        for (int x = 0; x < En; x++)
            if (r >= g_off[x] && r < g_off[x] + g_cnt[x]) { e = x; break; }
        g_tile_expert[t] = e;
    }
}

__global__ void k_scatter() {
    int i = blockIdx.x * blockDim.x + threadIdx.x;
    if (i >= Tn * Kn) return;
    int e = g_eidx[i];
    int row = g_off[e] + g_pos[i];
    g_row_token[row] = i >> 2;
    g_row_rw[row]    = g_rw[i];
}

// ---------------- conversions ----------------
// transpose + fp16 round: W[e][Kd][Nd] fp32 -> WT[e][ndst][Kd] fp16.
// ILV=1 interleaves gate/up columns: dst col = 2*j (gate) / 2*(j-HALF)+1 (up)
template<int ILV>
__global__ void k_thalf(const float* __restrict__ W, __half* __restrict__ o,
                        int Kd, int Nd, int HALF) {
    __shared__ float s[32][33];
    int e = blockIdx.z;
    const float* Wp = W + (size_t)e * Kd * Nd;
    int n0 = blockIdx.x * 32, k0 = blockIdx.y * 32;
    int tx = threadIdx.x, ty = threadIdx.y;
    #pragma unroll
    for (int j = 0; j < 4; j++)
        s[ty + 8*j][tx] = Wp[(size_t)(k0 + ty + 8*j) * Nd + n0 + tx];
    __syncthreads();
    size_t ob = (size_t)e * Nd * Kd;
    #pragma unroll
    for (int j = 0; j < 4; j++) {
        float v = s[tx][ty + 8*j];
        int jsrc = n0 + ty + 8*j;
        int nd = ILV ? (jsrc < HALF ? 2*jsrc : 2*(jsrc - HALF) + 1) : jsrc;
        o[ob + (size_t)nd * Kd + k0 + tx] = __float2half_rn(v);
    }
}

// hidden -> fp16
__global__ void k_half_hid(const float* __restrict__ hs) {
    int row = blockIdx.y;
    int c = blockIdx.x * 256 + threadIdx.x;
    g_hid[(size_t)row * Hn + c] = __float2half_rn(hs[(size_t)row * Hn + c]);
}

// gather fp16 hidden rows -> dispatched rows (zeros on padding)
__global__ void k_gather_h() {
    int row = blockIdx.x;
    int tid = threadIdx.x;   // 256 threads x 16B = 4096B = Hn halves
    int tok = g_row_token[row];
    int4* d = (int4*)(g_disp + (size_t)row * Hn);
    if (tok >= 0) d[tid] = ((const int4*)(g_hid + (size_t)tok * Hn))[tid];
    else          d[tid] = make_int4(0,0,0,0);
}

// ---------------- fp16 GEMM: C = A * B^T ----------------
// CTA tile 128x128, K-chunk 64 (SW128 from TMA), 3-stage pipeline (32KB/stage),
// 2 CTAs/SM. 8 warps (2m x 4n), warp tile 64x32, fp32 accumulators.
// FUSE=1: interleaved (gate,up) pairs -> SwiGLU -> fp16 out.
// FUSE=2: expert scatter: atomicAdd(out[token], rw * v)   (skip padding rows)
// FUSE=3: shared scatter: atomicAdd(out[row],  gate * v)
#define STAGE_BYTES 32768
#define SMEM_CTRL   1024
#define NSTAGE      3
#define GEMM_SMEM   (SMEM_CTRL + NSTAGE*STAGE_BYTES)

template<int GROUPED, int FUSE>
__global__ void __launch_bounds__(256, 2) k_mma(
    const __grid_constant__ CUtensorMap mA,
    const __grid_constant__ CUtensorMap mB,
    float* __restrict__ C, __half* __restrict__ Ch,
    int Kdim, int NcolsC)
{
    extern __shared__ __align__(1024) char smem[];
    const int mtile = blockIdx.y;
    int eid = 0;
    if (GROUPED) { eid = g_tile_expert[mtile]; if (eid < 0) return; }
    const int m0 = mtile * 128;
    const int n0 = blockIdx.x * 128;
    const int tid  = threadIdx.x;
    const int wid  = tid >> 5;
    const int lane = tid & 31;
    const int mw = (wid >> 2) * 64;
    const int nw = (wid & 3) * 32;
    const uint32_t sb = s2u(smem);
    if (tid == 0) {
        #pragma unroll
        for (int s = 0; s < NSTAGE; s++) {
            MBARRIER_INIT(sb + 8*s, 1);
            MBARRIER_INIT(sb + 64 + 8*s, 256);
        }
        FENCE_PROXY_ASYNC();
    }
    __syncthreads();

    const int nch = Kdim >> 6;
    const uint32_t st0 = sb + SMEM_CTRL;

    if (tid == 0) {
        #pragma unroll
        for (int c = 0; c < NSTAGE; c++) {
            uint32_t st = st0 + c * STAGE_BYTES;
            int kc = c << 6;
            MBARRIER_EXPECT_TX(sb + 8*c, STAGE_BYTES);
            tma3(st +     0, &mA, kc, m0, 0,   sb + 8*c);
            tma3(st + 16384, &mB, kc, n0, eid, sb + 8*c);
        }
    }

    float acc[4][4][4];
    #pragma unroll
    for (int i = 0; i < 4; i++)
        #pragma unroll
        for (int j = 0; j < 4; j++)
            #pragma unroll
            for (int q = 0; q < 4; q++) acc[i][j][q] = 0.f;

    const int r15 = lane & 15;
    const int cs  = lane >> 4;

    int s = 0, ph = 0;
    for (int c = 0; c < nch; c++) {
        MBARRIER_WAIT_PARITY(sb + 8*s, ph);
        const uint32_t st = st0 + s * STAGE_BYTES;
        #pragma unroll
        for (int kk = 0; kk < 4; kk++) {
            uint32_t aa[16], bb[8];
            #pragma unroll
            for (int mi = 0; mi < 4; mi++) {
                int row = mw + mi * 16 + r15;
                uint32_t off = row * 128 + ((((kk << 1) | cs) ^ (row & 7)) << 4);
                ldsm4(aa + 4*mi, st + off);
            }
            #pragma unroll
            for (int nj = 0; nj < 2; nj++) {
                int row = nw + nj * 16 + r15;
                uint32_t off = row * 128 + ((((kk << 1) | cs) ^ (row & 7)) << 4);
                ldsm4(bb + 4*nj, st + 16384 + off);
            }
            #pragma unroll
            for (int mi = 0; mi < 4; mi++) {
                #pragma unroll
                for (int ni = 0; ni < 4; ni++) {
                    int nj = ni >> 1, hf = ni & 1;
                    mma_f16(acc[mi][ni], aa + 4*mi, bb[4*nj + hf], bb[4*nj + 2 + hf]);
                }
            }
        }
        MBARRIER_ARRIVE(sb + 64 + 8*s);
        if (tid == 0 && c + NSTAGE < nch) {
            MBARRIER_WAIT_PARITY(sb + 64 + 8*s, ph);
            int kc = (c + NSTAGE) << 6;
            MBARRIER_EXPECT_TX(sb + 8*s, STAGE_BYTES);
            tma3(st +     0, &mA, kc, m0, 0,   sb + 8*s);
            tma3(st + 16384, &mB, kc, n0, eid, sb + 8*s);
        }
        if (++s == NSTAGE) { s = 0; ph ^= 1; }
    }

    // epilogue
    const int er = lane >> 2;
    const int ec = (lane & 3) << 1;
    #pragma unroll
    for (int mi = 0; mi < 4; mi++) {
        int r0 = m0 + mw + mi * 16 + er;
        int tok0 = 0, tok1 = 0;
        float w0 = 0.f, w1 = 0.f;
        if (FUSE == 2) {
            tok0 = g_row_token[r0];      w0 = g_row_rw[r0];
            tok1 = g_row_token[r0 + 8];  w1 = g_row_rw[r0 + 8];
        } else if (FUSE == 3) {
            tok0 = r0; tok1 = r0 + 8;
            w0 = g_gate[tok0]; w1 = g_gate[tok1];
        }
        #pragma unroll
        for (int ni = 0; ni < 4; ni++) {
            float v0 = acc[mi][ni][0], v1 = acc[mi][ni][1];
            float v2 = acc[mi][ni][2], v3 = acc[mi][ni][3];
            if (FUSE == 1) {
                // interleaved: even col = gate, odd = up; thread owns one pair
                int j = (n0 + nw + ni * 8 + ec) >> 1;
                float a0 = v0 / (1.f + expf(-v0)) * v1;
                float a1 = v2 / (1.f + expf(-v2)) * v3;
                Ch[(size_t)r0 * NcolsC + j]       = __float2half_rn(a0);
                Ch[(size_t)(r0 + 8) * NcolsC + j] = __float2half_rn(a1);
            } else if (FUSE == 2 || FUSE == 3) {
                int col = n0 + nw + ni * 8 + ec;
                if (FUSE == 3 || tok0 >= 0) {
                    atomicAdd(C + (size_t)tok0 * NcolsC + col,     w0 * v0);
                    atomicAdd(C + (size_t)tok0 * NcolsC + col + 1, w0 * v1);
                }
                if (FUSE == 3 || tok1 >= 0) {
                    atomicAdd(C + (size_t)tok1 * NcolsC + col,     w1 * v2);
                    atomicAdd(C + (size_t)tok1 * NcolsC + col + 1, w1 * v3);
                }
            } else {
                int col = n0 + nw + ni * 8 + ec;
                *(float2*)(C + (size_t)r0 * NcolsC + col)       = make_float2(v0, v1);
                *(float2*)(C + (size_t)(r0 + 8) * NcolsC + col) = make_float2(v2, v3);
            }
        }
    }
}

// ---------------- host launch ----------------
typedef CUresult (*encode_fn_t)(CUtensorMap*, CUtensorMapDataType, cuuint32_t, void*,
                                const cuuint64_t*, const cuuint64_t*, const cuuint32_t*,
                                const cuuint32_t*, CUtensorMapInterleave, CUtensorMapSwizzle,
                                CUtensorMapL2promotion, CUtensorMapFloatOOBfill);

static void mkmap(encode_fn_t enc, CUtensorMap* m, void* ptr,
                  uint64_t d0, uint64_t d1, uint64_t d2) {
    cuuint64_t dims[3] = {d0, d1, d2};
    cuuint64_t str[2]  = {d0 * 2, d0 * d1 * 2};
    cuuint32_t box[3]  = {64, 128, 1};
    cuuint32_t es[3]   = {1, 1, 1};
    enc(m, CU_TENSOR_MAP_DATA_TYPE_FLOAT16, 3, ptr, dims, str, box, es,
        CU_TENSOR_MAP_INTERLEAVE_NONE, CU_TENSOR_MAP_SWIZZLE_128B,
        CU_TENSOR_MAP_L2_PROMOTION_L2_128B, CU_TENSOR_MAP_FLOAT_OOB_FILL_NONE);
}

extern "C" void kernel_launch(void* const* d_in, const int* in_sizes, int n_in,
                              void* d_out, int out_size)
{
    const float* hs  = (const float*)d_in[0];
    const float* rw  = (const float*)d_in[1];
    const float* gup = (const float*)d_in[2];
    const float* dwn = (const float*)d_in[3];
    const float* sgu = (const float*)d_in[4];
    const float* sdn = (const float*)d_in[5];
    const float* sgw = (const float*)d_in[6];
    float* out = (float*)d_out;

    void* fp = nullptr;
    cudaDriverEntryPointQueryResult qr;
    cudaGetDriverEntryPointByVersion("cuTensorMapEncodeTiled", &fp, 12000,
                                     cudaEnableDefault, &qr);
    encode_fn_t enc = (encode_fn_t)fp;

    void *p_gupT, *p_dwnT, *p_sguT, *p_sdnT, *p_hid, *p_disp, *p_act, *p_sact;
    cudaGetSymbolAddress(&p_gupT, g_gupT);
    cudaGetSymbolAddress(&p_dwnT, g_dwnT);
    cudaGetSymbolAddress(&p_sguT, g_sguT);
    cudaGetSymbolAddress(&p_sdnT, g_sdnT);
    cudaGetSymbolAddress(&p_hid,  g_hid);
    cudaGetSymbolAddress(&p_disp, g_disp);
    cudaGetSymbolAddress(&p_act,  g_act);
    cudaGetSymbolAddress(&p_sact, g_sact);

    CUtensorMap mDisp, mGup, mAct, mDwn, mHid, mSgu, mSact, mSdn;
    mkmap(enc, &mDisp, p_disp, Hn,  RPAD, 1);
    mkmap(enc, &mGup,  p_gupT, Hn,  F2n,  En);
    mkmap(enc, &mAct,  p_act,  Fn,  RPAD, 1);
    mkmap(enc, &mDwn,  p_dwnT, Fn,  Hn,   En);
    mkmap(enc, &mHid,  p_hid,  Hn,  Tn,   1);
    mkmap(enc, &mSgu,  p_sguT, Hn,  FS2n, 1);
    mkmap(enc, &mSact, p_sact, FSn, Tn,   1);
    mkmap(enc, &mSdn,  p_sdnT, FSn, Hn,   1);

    cudaFuncSetAttribute(k_mma<0,1>, cudaFuncAttributeMaxDynamicSharedMemorySize, GEMM_SMEM);
    cudaFuncSetAttribute(k_mma<0,3>, cudaFuncAttributeMaxDynamicSharedMemorySize, GEMM_SMEM);
    cudaFuncSetAttribute(k_mma<1,1>, cudaFuncAttributeMaxDynamicSharedMemorySize, GEMM_SMEM);
    cudaFuncSetAttribute(k_mma<1,2>, cudaFuncAttributeMaxDynamicSharedMemorySize, GEMM_SMEM);

    // routing + dispatch + output zero-fill
    k_init<<<(RPAD + 255) / 256, 256>>>();
    k_zero<<<(Tn * Hn / 4) / 256, 256>>>(out);
    k_router<<<Tn, 128>>>(hs, rw, sgw);
    k_scan<<<1, 1>>>();
    k_scatter<<<64, 256>>>();

    // conversions (weights: transpose + fp16; gate_up matrices interleaved)
    dim3 tb(32, 8);
    k_thalf<1><<<dim3(F2n/32,  Hn/32,  En), tb>>>(gup, (__half*)p_gupT, Hn,  F2n,  Fn);
    k_thalf<0><<<dim3(Hn/32,   Fn/32,  En), tb>>>(dwn, (__half*)p_dwnT, Fn,  Hn,   0);
    k_thalf<1><<<dim3(FS2n/32, Hn/32,  1 ), tb>>>(sgu, (__half*)p_sguT, Hn,  FS2n, FSn);
    k_thalf<0><<<dim3(Hn/32,   FSn/32, 1 ), tb>>>(sdn, (__half*)p_sdnT, FSn, Hn,   0);
    k_half_hid<<<dim3(Hn/256, Tn), 256>>>(hs);
    k_gather_h<<<RPAD, 256>>>();

    // expert path: fused gate_up+SwiGLU -> down (atomic scatter to out)
    k_mma<1,1><<<dim3(F2n/128, MT_E), 256, GEMM_SMEM>>>(mDisp, mGup,
        nullptr, (__half*)p_act, Hn, Fn);
    k_mma<1,2><<<dim3(Hn/128, MT_E), 256, GEMM_SMEM>>>(mAct, mDwn,
        out, nullptr, Fn, Hn);

    // shared expert path: fused gate_up+SwiGLU -> down (gated atomic scatter)
    k_mma<0,1><<<dim3(FS2n/128, Tn/128), 256, GEMM_SMEM>>>(mHid, mSgu,
        nullptr, (__half*)p_sact, Hn, FSn);
    k_mma<0,3><<<dim3(Hn/128, Tn/128), 256, GEMM_SMEM>>>(mSact, mSdn,
        out, nullptr, FSn, Hn);
}